// round 8
// baseline (speedup 1.0000x reference)
#include <cuda_runtime.h>
#include <math.h>

#define BB 2
#define NN 8192
#define NPT (BB*NN)
#define KNN 10
#define GRID 16
#define GC (GRID*GRID*GRID)
#define HCELL 0.0625f
#define NBLK 128
#define NTG 512
#define NTM 512
#define SCAP 2816
#define CB 48

// ---------------- device scratch ----------------
__device__ float4 g_sp4[NPT];
__device__ int    g_sidx[NPT];
__device__ int    g_cnt[BB*GC];      // INVARIANT: zero at kernel entry
__device__ int2   g_range[BB*GC];
__device__ int    g_cur[BB*GC];
__device__ double g_cacc[BB][4];
__device__ float  g_geom[NPT * 6];
__device__ int    g_mtype;
__device__ float  g_T;
__device__ unsigned g_barcnt = 0;
__device__ unsigned g_sense  = 0;

// ---------------- grid barrier ----------------
__device__ __forceinline__ void gridbar() {
    __syncthreads();
    if (threadIdx.x == 0) {
        __threadfence();
        unsigned gen = atomicAdd(&g_sense, 0u);
        if (atomicAdd(&g_barcnt, 1u) == NBLK - 1) {
            g_barcnt = 0;
            __threadfence();
            atomicAdd(&g_sense, 1u);
        } else {
            while (atomicAdd(&g_sense, 0u) == gen) {}
        }
        __threadfence();
    }
    __syncthreads();
}

// ---------------- f32x2 helpers ----------------
#define FMA2(d, a, b) asm("fma.rn.f32x2 %0, %1, %2, %3;" : "=l"(d) : "l"(a), "l"(b), "l"(d))
__device__ __forceinline__ unsigned long long pack2(float v) {
    unsigned long long r; unsigned u = __float_as_uint(v);
    asm("mov.b64 %0, {%1, %1};" : "=l"(r) : "r"(u));
    return r;
}
__device__ __forceinline__ void unpack2(unsigned long long v, float& lo, float& hi) {
    unsigned a, b;
    asm("mov.b64 {%0, %1}, %2;" : "=r"(a), "=r"(b) : "l"(v));
    lo = __uint_as_float(a); hi = __uint_as_float(b);
}

__device__ __forceinline__ int cell_of(float x, float y, float z) {
    int cx = min(GRID - 1, max(0, (int)(x * (float)GRID)));
    int cy = min(GRID - 1, max(0, (int)(y * (float)GRID)));
    int cz = min(GRID - 1, max(0, (int)(z * (float)GRID)));
    return (cz * GRID + cy) * GRID + cx;
}

__device__ __forceinline__ bool read_mask(const void* mp, int i, int mt) {
    if (mt & 1) return ((const unsigned char*)mp)[i] != 0;
    if (mt & 2) return ((const float*)mp)[i] != 0.0f;
    return ((const int*)mp)[i] != 0;
}

// ---------------- analytic eigenvalues of symmetric 3x3 (fp64) ----------------
__device__ __forceinline__ float curv_from_cov(float c00, float c01, float c02,
                                               float c11, float c12, float c22) {
    double a00 = c00, a01 = c01, a02 = c02, a11 = c11, a12 = c12, a22 = c22;
    double p1 = a01 * a01 + a02 * a02 + a12 * a12;
    double q  = (a00 + a11 + a22) / 3.0;
    double d0 = a00 - q, d1 = a11 - q, d2v = a22 - q;
    double p2 = d0 * d0 + d1 * d1 + d2v * d2v + 2.0 * p1;
    double emin, emax;
    if (!(p2 > 0.0)) { emin = q; emax = q; }
    else {
        double p = sqrt(p2 / 6.0);
        double ip = 1.0 / p;
        double b00 = d0 * ip, b11 = d1 * ip, b22 = d2v * ip;
        double b01 = a01 * ip, b02 = a02 * ip, b12 = a12 * ip;
        double detB = b00 * (b11 * b22 - b12 * b12)
                    - b01 * (b01 * b22 - b12 * b02)
                    + b02 * (b01 * b12 - b11 * b02);
        double r = 0.5 * detB;
        r = fmin(1.0, fmax(-1.0, r));
        double phi = acos(r) / 3.0;
        emax = q + 2.0 * p * cos(phi);
        emin = q + 2.0 * p * cos(phi + 2.0943951023931953);
    }
    float e0 = (float)emin, e2 = (float)emax;
    return e0 / (e2 + 1e-8f);
}

// candidate eval with sorted-insert (fallback path only)
#define CAND(PJ, JJ) do {                                                        \
    float sqj = fabsf((PJ).w);                                                   \
    float Tv  = (__float_as_uint((PJ).w) & 0x80000000u)                          \
                ? Tloc : __int_as_float(0xff800000);                             \
    float dot = fmaf(pix, (PJ).x, fmaf(piy, (PJ).y, piz * (PJ).z));              \
    float d2  = fmaf(-2.0f, dot, piw + sqj);                                     \
    if (d2 <= Tv) cnt++;                                                         \
    float d2c = fmaxf(d2, 0.0f);                                                 \
    unsigned long long key =                                                     \
        ((unsigned long long)__float_as_uint(d2c) << 32) | (unsigned)(JJ);       \
    if (key < best[KNN - 1]) {                                                   \
        _Pragma("unroll")                                                        \
        for (int _k = 0; _k < KNN; _k++) {                                       \
            if (key < best[_k]) {                                                \
                unsigned long long _t = best[_k]; best[_k] = key; key = _t;      \
            }                                                                    \
        }                                                                        \
    }                                                                            \
} while (0)

// merge top-10 across 4 lanes; owner pops + accumulates covariance
#define MERGE10() do {                                                           \
    c00 = c01 = c02 = c11 = c12 = c22 = 0.0f;                                    \
    d10key = 0xFFFFFFFFFFFFFFFFull;                                              \
    _Pragma("unroll")                                                            \
    for (int _rd = 0; _rd < KNN; _rd++) {                                        \
        unsigned long long m = best[0];                                          \
        m = min(m, __shfl_xor_sync(gm, m, 1));                                   \
        m = min(m, __shfl_xor_sync(gm, m, 2));                                   \
        bool real = ((unsigned)(m & 0xFFFFFFFFull)) != 0xFFFFFFFFu;              \
        if (m == best[0] && real) {                                              \
            int _j = (int)(unsigned)(m & 0xFFFFFFFFull);                         \
            float4 _q = g_sp4[boff + _j];                                        \
            float dx = _q.x - pix, dy = _q.y - piy, dz = _q.z - piz;             \
            c00 = fmaf(dx, dx, c00); c01 = fmaf(dx, dy, c01);                    \
            c02 = fmaf(dx, dz, c02); c11 = fmaf(dy, dy, c11);                    \
            c12 = fmaf(dy, dz, c12); c22 = fmaf(dz, dz, c22);                    \
            _Pragma("unroll")                                                    \
            for (int _k = 0; _k < KNN - 1; _k++) best[_k] = best[_k + 1];        \
            best[KNN - 1] = 0xFFFFFFFFFFFFFFFFull;                               \
        }                                                                        \
        d10key = m;                                                              \
    }                                                                            \
} while (0)

__device__ __forceinline__ float wall_g(float pix, float piy, float piz,
                                        int cix, int ciy, int ciz, int R) {
    float g = __int_as_float(0x7f800000);
    if (cix - R > 0)        g = fminf(g, pix - (float)(cix - R) * HCELL);
    if (cix + R < GRID - 1) g = fminf(g, (float)(cix + R + 1) * HCELL - pix);
    if (ciy - R > 0)        g = fminf(g, piy - (float)(ciy - R) * HCELL);
    if (ciy + R < GRID - 1) g = fminf(g, (float)(ciy + R + 1) * HCELL - piy);
    if (ciz - R > 0)        g = fminf(g, piz - (float)(ciz - R) * HCELL);
    if (ciz + R < GRID - 1) g = fminf(g, (float)(ciz + R + 1) * HCELL - piz);
    return g;
}

// dynamic smem layout for k_main
#define SM_SPT   0
#define SM_SJ    45056
#define SM_SCELL 56320
#define SM_CBUF  60416
#define SM_SCNT  109568
#define SM_ROWJ  110080
#define SM_ROWL  110336
#define SM_ROWB  110592
#define SM_HJ    110848
#define SM_HL    110912
#define SM_HP    110976
#define SM_TOT   111048
#define SMEM_MAIN 111104

// ================= kernel 1: prep + region-tiled geom (compaction kNN) =================
__global__ void __launch_bounds__(NTG)
k_main(const float* __restrict__ pts, const void* __restrict__ mask) {
    extern __shared__ char smraw[];
    float4* spt     = (float4*)(smraw + SM_SPT);
    int*    sj      = (int*)  (smraw + SM_SJ);
    int2*   scell   = (int2*) (smraw + SM_SCELL);
    unsigned long long* cbuf = (unsigned long long*)(smraw + SM_CBUF);
    int*    scnt    = (int*)  (smraw + SM_SCNT);
    int*    rowjst  = (int*)  (smraw + SM_ROWJ);
    int*    rowlen  = (int*)  (smraw + SM_ROWL);
    int*    rowbase = (int*)  (smraw + SM_ROWB);
    int*    hjst    = (int*)  (smraw + SM_HJ);
    int*    hlen    = (int*)  (smraw + SM_HL);
    int*    hpre    = (int*)  (smraw + SM_HP);
    int*    sTotal  = (int*)  (smraw + SM_TOT);

    const int tid = threadIdx.x;
    const int bid = blockIdx.x;
    const int gid = bid * NTG + tid;

    // ---------- phase 1: cell counts + mask dtype detect ----------
    {
        bool act = gid < NPT;
        unsigned char mb = 0;
        if (act) {
            float x = pts[gid * 3 + 0], y = pts[gid * 3 + 1], z = pts[gid * 3 + 2];
            mb = ((const unsigned char*)mask)[gid];
            atomicAdd(&g_cnt[(gid >> 13) * GC + cell_of(x, y, z)], 1);
        }
        int r = gid & 3;
        unsigned m1 = __ballot_sync(0xFFFFFFFFu, act && (r == 1) && mb);
        unsigned m2 = __ballot_sync(0xFFFFFFFFu, act && (r >= 2) && mb);
        if ((tid & 31) == 0 && (m1 | m2))
            atomicOr(&g_mtype, (m1 ? 1 : 0) | (m2 ? 2 : 0));
    }
    gridbar();

    // ---------- phase 2: scan (blocks 0,1) + restore invariants ----------
    if (bid < BB) {
        int* part = sj;
        int base = bid * GC + tid * 8;
        int loc[8]; int s = 0;
#pragma unroll
        for (int k = 0; k < 8; k++) { loc[k] = s; s += g_cnt[base + k]; }
        part[tid] = s;
        __syncthreads();
        for (int d = 1; d < NTG; d <<= 1) {
            int v = (tid >= d) ? part[tid - d] : 0;
            __syncthreads();
            part[tid] += v;
            __syncthreads();
        }
        int off = part[tid] - s;
#pragma unroll
        for (int k = 0; k < 8; k++) {
            int st = off + loc[k];
            int ln = g_cnt[base + k];
            g_range[base + k] = make_int2(st, st + ln);
            g_cur[base + k]   = st;
            g_cnt[base + k]   = 0;
        }
        if (gid == 0) {
            for (int b = 0; b < BB; b++)
                for (int c = 0; c < 4; c++) g_cacc[b][c] = 0.0;
            const float R = 0.02f;
            float t = __fmul_rn(R, R);
            while (__fsqrt_rn(t) >= R) t = __uint_as_float(__float_as_uint(t) - 1u);
            for (;;) {
                float nt = __uint_as_float(__float_as_uint(t) + 1u);
                if (__fsqrt_rn(nt) < R) t = nt; else break;
            }
            g_T = t;
        }
    }
    gridbar();

    // ---------- phase 3: scatter + masked centroid ----------
    if (gid < NPT) {
        int mt = g_mtype;
        float x = pts[gid * 3 + 0], y = pts[gid * 3 + 1], z = pts[gid * 3 + 2];
        float sq = __fadd_rn(__fadd_rn(__fmul_rn(x, x), __fmul_rn(y, y)), __fmul_rn(z, z));
        int b = gid >> 13;
        int cell = b * GC + cell_of(x, y, z);
        bool mk = read_mask(mask, gid, mt);
        float wv = mk ? __uint_as_float(__float_as_uint(sq) | 0x80000000u) : sq;
        int pos = atomicAdd(&g_cur[cell], 1);
        int dst = b * NN + pos;
        g_sp4[dst]  = make_float4(x, y, z, wv);
        g_sidx[dst] = gid;
        double vx = mk ? (double)x : 0.0, vy = mk ? (double)y : 0.0;
        double vz = mk ? (double)z : 0.0, vc = mk ? 1.0 : 0.0;
#pragma unroll
        for (int o = 16; o > 0; o >>= 1) {
            vx += __shfl_down_sync(0xFFFFFFFFu, vx, o);
            vy += __shfl_down_sync(0xFFFFFFFFu, vy, o);
            vz += __shfl_down_sync(0xFFFFFFFFu, vz, o);
            vc += __shfl_down_sync(0xFFFFFFFFu, vc, o);
        }
        if ((tid & 31) == 0) {
            atomicAdd(&g_cacc[b][0], vx);
            atomicAdd(&g_cacc[b][1], vy);
            atomicAdd(&g_cacc[b][2], vz);
            atomicAdd(&g_cacc[b][3], vc);
        }
    }
    gridbar();

    // ---------- phase 4: region-tiled exact 10-NN + density ----------
    const int b   = bid >> 6;
    const int rid = bid & 63;
    const int hx0 = (rid & 3) * 4, hy0 = ((rid >> 2) & 3) * 4, hz0 = (rid >> 4) * 4;
    const int gx0 = max(hx0 - 2, 0), gx1 = min(hx0 + 5, GRID - 1);
    const int gy0 = max(hy0 - 2, 0), gy1 = min(hy0 + 5, GRID - 1);
    const int gz0 = max(hz0 - 2, 0), gz1 = min(hz0 + 5, GRID - 1);
    const int nx = gx1 - gx0 + 1, ny = gy1 - gy0 + 1, nz = gz1 - gz0 + 1;
    const int nrow = ny * nz;
    const int boff = b * NN, cbase = b * GC;
    const float Tloc = g_T;

    if (tid < nrow) {
        int z = gz0 + tid / ny, y = gy0 + tid % ny;
        int crow = cbase + (z * GRID + y) * GRID;
        int jst = g_range[crow + gx0].x;
        int jen = g_range[crow + gx1].y;
        rowjst[tid] = jst;
        rowlen[tid] = jen - jst;
    }
    if (tid >= 64 && tid < 80) {
        int hr = tid - 64;
        int z = hz0 + (hr >> 2), y = hy0 + (hr & 3);
        int crow = cbase + (z * GRID + y) * GRID;
        int jst = g_range[crow + hx0].x;
        hjst[hr] = jst;
        hlen[hr] = g_range[crow + hx0 + 3].y - jst;
    }
    __syncthreads();
    if (tid == 0) {
        int acc = 0;
        for (int r = 0; r < nrow; r++) { int l = rowlen[r]; rowbase[r] = acc; acc += l; }
        *sTotal = acc;
    }
    if (tid == 1) {
        int acc = 0;
        for (int r = 0; r < 16; r++) { hpre[r] = acc; acc += hlen[r]; }
        hpre[16] = acc;
    }
    __syncthreads();
    const bool ovf = *sTotal > SCAP;

    if (!ovf) {
        int w = tid >> 5, lane = tid & 31;
        for (int rr = w; rr < nrow; rr += 16) {
            int jst = rowjst[rr], len = rowlen[rr], rb = rowbase[rr];
            for (int k = lane; k < len; k += 32) {
                spt[rb + k] = g_sp4[boff + jst + k];
                sj [rb + k] = jst + k;
            }
        }
        for (int c = tid; c < nrow * nx; c += NTG) {
            int rr = c / nx, lx = c % nx;
            int z = gz0 + rr / ny, y = gy0 + rr % ny;
            int2 gr = g_range[cbase + (z * GRID + y) * GRID + gx0 + lx];
            int sh = rowbase[rr] - rowjst[rr];
            scell[rr * 8 + lx] = make_int2(gr.x + sh, gr.y + sh);
        }
    }
    __syncthreads();

    const int M = hpre[16];
    const int grp = tid >> 2, l4 = tid & 3;
    const unsigned gm = 0xFu << ((tid & 31) & ~3);
    unsigned long long* cb = cbuf + grp * CB;

    for (int task = grp; task < M; task += NTG / 4) {
        int hr = 0;
        while (task >= hpre[hr + 1]) hr++;
        int jp = hjst[hr] + task - hpre[hr];

        float4 pi = g_sp4[boff + jp];
        const float pix = pi.x, piy = pi.y, piz = pi.z, piw = fabsf(pi.w);

        const int cix = min(GRID - 1, max(0, (int)(pix * (float)GRID)));
        const int ciy = min(GRID - 1, max(0, (int)(piy * (float)GRID)));
        const int ciz = min(GRID - 1, max(0, (int)(piz * (float)GRID)));

        // statistical gate radius (~22 expected neighbors, wall-clip aware)
        float r_est = 0.075f;
#pragma unroll
        for (int it = 0; it < 2; it++) {
            float fx = (fminf(pix + r_est, 1.0f) - fmaxf(pix - r_est, 0.0f)) / (2.0f * r_est);
            float fy = (fminf(piy + r_est, 1.0f) - fmaxf(piy - r_est, 0.0f)) / (2.0f * r_est);
            float fz = (fminf(piz + r_est, 1.0f) - fmaxf(piz - r_est, 0.0f)) / (2.0f * r_est);
            r_est = cbrtf(6.4e-4f / fmaxf(fx * fy * fz, 0.125f));
        }
        const float t_est = r_est * r_est;

        int cnt = 0;
        float c00, c01, c02, c11, c12, c22;
        unsigned long long d10key;
        bool done = false;

        // ======== gated attempt: scan R=2 box, compact passers ========
        {
            if (l4 == 0) scnt[grp] = 0;
            __syncwarp(gm);

            const int x0 = max(cix - 2, 0), x1 = min(cix + 2, GRID - 1);
            const int y0 = max(ciy - 2, 0), y1 = min(ciy + 2, GRID - 1);
            const int z0 = max(ciz - 2, 0), z1 = min(ciz + 2, GRID - 1);
            const int wy = y1 - y0 + 1, wz = z1 - z0 + 1;
            const int nrows = wy * wz;

            for (int q = l4; q < nrows; q += 4) {
                int zz = z0 + q / wy, yy = y0 + q % wy;
                int st, en;
                if (!ovf) {
                    int rr = (zz - gz0) * ny + (yy - gy0);
                    st = scell[rr * 8 + (x0 - gx0)].x;
                    en = scell[rr * 8 + (x1 - gx0)].y;
                } else {
                    int crow = cbase + (zz * GRID + yy) * GRID;
                    st = g_range[crow + x0].x;
                    en = g_range[crow + x1].y;
                }
                for (int u = st; u < en; u++) {
                    float4 pj; int jidx;
                    if (!ovf) { pj = spt[u]; jidx = sj[u]; }
                    else      { pj = g_sp4[boff + u]; jidx = u; }
                    float sqj = fabsf(pj.w);
                    float Tv  = (__float_as_uint(pj.w) & 0x80000000u)
                                ? Tloc : __int_as_float(0xff800000);
                    float dot = fmaf(pix, pj.x, fmaf(piy, pj.y, piz * pj.z));
                    float d2  = fmaf(-2.0f, dot, piw + sqj);
                    if (d2 <= Tv) cnt++;
                    float d2c = fmaxf(d2, 0.0f);
                    if (d2c <= t_est) {
                        int off = atomicAdd(&scnt[grp], 1);
                        if (off < CB)
                            cb[off] = ((unsigned long long)__float_as_uint(d2c) << 32)
                                      | (unsigned)jidx;
                    }
                }
            }
            __syncwarp(gm);
            int nc = scnt[grp];

            if (nc >= KNN && nc <= CB) {
                unsigned long long best[KNN];
#pragma unroll
                for (int k = 0; k < KNN; k++) best[k] = 0xFFFFFFFFFFFFFFFFull;
                for (int u = l4; u < nc; u += 4) {
                    unsigned long long key = cb[u];
                    if (key < best[KNN - 1]) {
#pragma unroll
                        for (int k = 0; k < KNN; k++) {
                            if (key < best[k]) {
                                unsigned long long t = best[k]; best[k] = key; key = t;
                            }
                        }
                    }
                }
                MERGE10();
                float g = wall_g(pix, piy, piz, cix, ciy, ciz, 2);
                float d10 = __uint_as_float((unsigned)(d10key >> 32));
                if (d10 < g * g) done = true;
            }
        }

        // ======== fallback / expansion: ungated sorted-insert scans ========
        if (!done) {
            for (int R = 2;; R++) {
                unsigned long long best[KNN];
#pragma unroll
                for (int k = 0; k < KNN; k++) best[k] = 0xFFFFFFFFFFFFFFFFull;
                cnt = 0;

                const int x0 = max(cix - R, 0), x1 = min(cix + R, GRID - 1);
                const int y0 = max(ciy - R, 0), y1 = min(ciy + R, GRID - 1);
                const int z0 = max(ciz - R, 0), z1 = min(ciz + R, GRID - 1);
                const int wy = y1 - y0 + 1, wz = z1 - z0 + 1;
                const int nrows = wy * wz;

                if (R == 2 && !ovf) {
                    for (int q = l4; q < nrows; q += 4) {
                        int zz = z0 + q / wy, yy = y0 + q % wy;
                        int rr = (zz - gz0) * ny + (yy - gy0);
                        int st = scell[rr * 8 + (x0 - gx0)].x;
                        int en = scell[rr * 8 + (x1 - gx0)].y;
                        for (int u = st; u < en; u++) {
                            float4 pj = spt[u];
                            CAND(pj, sj[u]);
                        }
                    }
                } else {
                    for (int q = l4; q < nrows; q += 4) {
                        int zz = z0 + q / wy, yy = y0 + q % wy;
                        int crow = cbase + (zz * GRID + yy) * GRID;
                        int jst = g_range[crow + x0].x;
                        int jen = g_range[crow + x1].y;
                        for (int j2 = jst; j2 < jen; j2++) {
                            float4 pj = g_sp4[boff + j2];
                            CAND(pj, j2);
                        }
                    }
                }

                MERGE10();
                float g = wall_g(pix, piy, piz, cix, ciy, ciz, R);
                bool filled = ((unsigned)(d10key & 0xFFFFFFFFull)) != 0xFFFFFFFFu;
                float d10 = __uint_as_float((unsigned)(d10key >> 32));
                if (filled && d10 < g * g) break;
                if (R >= GRID) break;
            }
        }

        // reduce density + covariance across 4 lanes
#pragma unroll
        for (int o = 1; o < 4; o <<= 1) {
            cnt += __shfl_xor_sync(gm, cnt, o);
            c00 += __shfl_xor_sync(gm, c00, o);
            c01 += __shfl_xor_sync(gm, c01, o);
            c02 += __shfl_xor_sync(gm, c02, o);
            c11 += __shfl_xor_sync(gm, c11, o);
            c12 += __shfl_xor_sync(gm, c12, o);
            c22 += __shfl_xor_sync(gm, c22, o);
        }

        if (l4 == 0) {
            int orig = g_sidx[boff + jp];
            c00 = __fdiv_rn(c00, 10.0f); c01 = __fdiv_rn(c01, 10.0f); c02 = __fdiv_rn(c02, 10.0f);
            c11 = __fdiv_rn(c11, 10.0f); c12 = __fdiv_rn(c12, 10.0f); c22 = __fdiv_rn(c22, 10.0f);
            float curv = curv_from_cov(c00, c01, c02, c11, c12, c22);

            double cm   = g_cacc[b][3];
            double cden = cm > 1.0 ? cm : 1.0;
            float cx = (float)(g_cacc[b][0] / cden);
            float cy = (float)(g_cacc[b][1] / cden);
            float cz = (float)(g_cacc[b][2] / cden);
            float rx = pix - cx, ry = piy - cy, rz = piz - cz;
            float distc = __fsqrt_rn(__fadd_rn(__fadd_rn(__fmul_rn(rx, rx), __fmul_rn(ry, ry)), __fmul_rn(rz, rz)));
            float horiz = __fsqrt_rn(__fadd_rn(__fmul_rn(rx, rx), __fmul_rn(ry, ry)));
            float rad   = atan2f(ry, rx);

            bool valid = cm > 0.0;
            g_geom[orig * 6 + 0] = valid ? distc : 0.0f;
            g_geom[orig * 6 + 1] = valid ? rz    : 0.0f;
            g_geom[orig * 6 + 2] = valid ? horiz : 0.0f;
            g_geom[orig * 6 + 3] = valid ? (float)cnt : 0.0f;
            g_geom[orig * 6 + 4] = valid ? curv  : 0.0f;
            g_geom[orig * 6 + 5] = valid ? rad   : 0.0f;
        }
    }
}

// ================= kernel 2: fused 2-layer MLP (f32x2 FMA, float4 k-unroll) =================
__global__ void __launch_bounds__(NTM) k_mlp(const float* __restrict__ feat,
                                             const float* __restrict__ W1,
                                             const float* __restrict__ b1,
                                             const float* __restrict__ W2,
                                             const float* __restrict__ b2,
                                             float* __restrict__ out) {
    extern __shared__ float sm[];
    float* sW1 = sm;             // 72*128 (rows 70,71 zero)
    float* sB1 = sm + 9216;      // 128
    float* sW2 = sm + 9344;      // 128*128
    float* sB2 = sm + 25728;     // 128
    float* sX  = sm + 25856;     // 128*72 (cols 70,71 zero)
    float* sH  = sm + 35072;     // 128*132

    int tid = threadIdx.x;
    for (int i = tid; i < 9216; i += NTM) sW1[i] = (i < 8960) ? W1[i] : 0.0f;
    for (int i = tid; i < 16384; i += NTM) sW2[i] = W2[i];
    if (tid < 128) { sB1[tid] = b1[tid]; sB2[tid] = b2[tid]; }

    int m0 = blockIdx.x * 128;
    for (int i = tid; i < 128 * 64; i += NTM) {
        int r = i >> 6, c = i & 63;
        sX[r * 72 + c] = feat[(m0 + r) * 64 + c];
    }
    for (int i = tid; i < 128 * 6; i += NTM) {
        int r = i / 6, c = i % 6;
        sX[r * 72 + 64 + c] = g_geom[(m0 + r) * 6 + c];
    }
    for (int i = tid; i < 256; i += NTM) {
        int r = i >> 1, c = 70 + (i & 1);
        sX[r * 72 + c] = 0.0f;
    }
    __syncthreads();

    int cg = tid & 31;   // cols cg*4 .. cg*4+3
    int rg = tid >> 5;   // rows rg*8 .. rg*8+7

    unsigned long long acc[8][2];
#pragma unroll
    for (int r = 0; r < 8; r++) { acc[r][0] = 0ull; acc[r][1] = 0ull; }

    for (int k = 0; k < 72; k += 4) {
        ulonglong2 w0 = *(const ulonglong2*)(sW1 + (k + 0) * 128 + cg * 4);
        ulonglong2 w1 = *(const ulonglong2*)(sW1 + (k + 1) * 128 + cg * 4);
        ulonglong2 w2 = *(const ulonglong2*)(sW1 + (k + 2) * 128 + cg * 4);
        ulonglong2 w3 = *(const ulonglong2*)(sW1 + (k + 3) * 128 + cg * 4);
#pragma unroll
        for (int r = 0; r < 8; r++) {
            float4 xv = *(const float4*)(sX + (rg * 8 + r) * 72 + k);
            unsigned long long xp;
            xp = pack2(xv.x); FMA2(acc[r][0], w0.x, xp); FMA2(acc[r][1], w0.y, xp);
            xp = pack2(xv.y); FMA2(acc[r][0], w1.x, xp); FMA2(acc[r][1], w1.y, xp);
            xp = pack2(xv.z); FMA2(acc[r][0], w2.x, xp); FMA2(acc[r][1], w2.y, xp);
            xp = pack2(xv.w); FMA2(acc[r][0], w3.x, xp); FMA2(acc[r][1], w3.y, xp);
        }
    }
    {
        float4 bv = *(const float4*)(sB1 + cg * 4);
#pragma unroll
        for (int r = 0; r < 8; r++) {
            float a0, a1, a2, a3;
            unpack2(acc[r][0], a0, a1);
            unpack2(acc[r][1], a2, a3);
            float4 h;
            h.x = fmaxf(a0 + bv.x, 0.0f);
            h.y = fmaxf(a1 + bv.y, 0.0f);
            h.z = fmaxf(a2 + bv.z, 0.0f);
            h.w = fmaxf(a3 + bv.w, 0.0f);
            *(float4*)(sH + (rg * 8 + r) * 132 + cg * 4) = h;
        }
    }
    __syncthreads();

#pragma unroll
    for (int r = 0; r < 8; r++) { acc[r][0] = 0ull; acc[r][1] = 0ull; }

    for (int k = 0; k < 128; k += 4) {
        ulonglong2 w0 = *(const ulonglong2*)(sW2 + (k + 0) * 128 + cg * 4);
        ulonglong2 w1 = *(const ulonglong2*)(sW2 + (k + 1) * 128 + cg * 4);
        ulonglong2 w2 = *(const ulonglong2*)(sW2 + (k + 2) * 128 + cg * 4);
        ulonglong2 w3 = *(const ulonglong2*)(sW2 + (k + 3) * 128 + cg * 4);
#pragma unroll
        for (int r = 0; r < 8; r++) {
            float4 hv = *(const float4*)(sH + (rg * 8 + r) * 132 + k);
            unsigned long long hp;
            hp = pack2(hv.x); FMA2(acc[r][0], w0.x, hp); FMA2(acc[r][1], w0.y, hp);
            hp = pack2(hv.y); FMA2(acc[r][0], w1.x, hp); FMA2(acc[r][1], w1.y, hp);
            hp = pack2(hv.z); FMA2(acc[r][0], w2.x, hp); FMA2(acc[r][1], w2.y, hp);
            hp = pack2(hv.w); FMA2(acc[r][0], w3.x, hp); FMA2(acc[r][1], w3.y, hp);
        }
    }
    {
        float4 bv = *(const float4*)(sB2 + cg * 4);
#pragma unroll
        for (int r = 0; r < 8; r++) {
            float a0, a1, a2, a3;
            unpack2(acc[r][0], a0, a1);
            unpack2(acc[r][1], a2, a3);
            float4 o;
            o.x = fmaxf(a0 + bv.x, 0.0f);
            o.y = fmaxf(a1 + bv.y, 0.0f);
            o.z = fmaxf(a2 + bv.z, 0.0f);
            o.w = fmaxf(a3 + bv.w, 0.0f);
            *(float4*)(out + (size_t)(m0 + rg * 8 + r) * 128 + cg * 4) = o;
        }
    }
}

// ---------------- launch ----------------
extern "C" void kernel_launch(void* const* d_in, const int* in_sizes, int n_in,
                              void* d_out, int out_size) {
    const float* points = (const float*)d_in[0];
    const float* feat   = (const float*)d_in[1];
    const void*  mask   = d_in[2];
    const float* W1     = (const float*)d_in[3];
    const float* b1     = (const float*)d_in[4];
    const float* W2     = (const float*)d_in[5];
    const float* b2     = (const float*)d_in[6];
    float* out = (float*)d_out;

    cudaFuncSetAttribute(k_main, cudaFuncAttributeMaxDynamicSharedMemorySize, SMEM_MAIN);
    cudaFuncSetAttribute(k_mlp,  cudaFuncAttributeMaxDynamicSharedMemorySize, 212992);

    k_main<<<NBLK, NTG, SMEM_MAIN>>>(points, mask);
    k_mlp <<<NPT / 128, NTM, 207872>>>(feat, W1, b1, W2, b2, out);
}

// round 9
// speedup vs baseline: 1.8371x; 1.8371x over previous
#include <cuda_runtime.h>
#include <math.h>

#define BB 2
#define NN 8192
#define NPT (BB*NN)
#define KNN 10
#define GRID 20
#define GC (GRID*GRID*GRID)
#define HCELL 0.05f
#define NBLKP 128
#define NTHRP 256
#define NTM 1024

// ---------------- device scratch ----------------
__device__ float4 g_sp4[NPT];        // sorted points (x,y,z, sq with sign bit = mask)
__device__ int    g_sidx[NPT];       // sorted -> original index
__device__ int    g_cnt[BB*GC];
__device__ int2   g_range[BB*GC];    // (start,end) within batch
__device__ int    g_cur[BB*GC];
__device__ double g_cacc[BB][4];     // masked centroid sums + count
__device__ float  g_geom[NPT * 6];
__device__ int    g_mtype;
__device__ float  g_T;
__device__ unsigned g_barcnt = 0;
__device__ unsigned g_sense  = 0;

// ---------------- grid barrier (co-resident blocks only) ----------------
__device__ __forceinline__ void gridbar() {
    __syncthreads();
    if (threadIdx.x == 0) {
        __threadfence();
        unsigned gen = atomicAdd(&g_sense, 0u);
        if (atomicAdd(&g_barcnt, 1u) == NBLKP - 1) {
            g_barcnt = 0;
            __threadfence();
            atomicAdd(&g_sense, 1u);
        } else {
            while (atomicAdd(&g_sense, 0u) == gen) {}
        }
        __threadfence();
    }
    __syncthreads();
}

// ---------------- f32x2 helpers ----------------
#define FMA2(d, a, b) asm("fma.rn.f32x2 %0, %1, %2, %3;" : "=l"(d) : "l"(a), "l"(b), "l"(d))
__device__ __forceinline__ unsigned long long pack2(float v) {
    unsigned long long r; unsigned u = __float_as_uint(v);
    asm("mov.b64 %0, {%1, %1};" : "=l"(r) : "r"(u));
    return r;
}
__device__ __forceinline__ void unpack2(unsigned long long v, float& lo, float& hi) {
    unsigned a, b;
    asm("mov.b64 {%0, %1}, %2;" : "=r"(a), "=r"(b) : "l"(v));
    lo = __uint_as_float(a); hi = __uint_as_float(b);
}

__device__ __forceinline__ int cell_of(float x, float y, float z) {
    int cx = min(GRID - 1, max(0, (int)(x * (float)GRID)));
    int cy = min(GRID - 1, max(0, (int)(y * (float)GRID)));
    int cz = min(GRID - 1, max(0, (int)(z * (float)GRID)));
    return (cz * GRID + cy) * GRID + cx;
}

__device__ __forceinline__ bool read_mask(const void* mp, int i, int mt) {
    if (mt & 1) return ((const unsigned char*)mp)[i] != 0;
    if (mt & 2) return ((const float*)mp)[i] != 0.0f;
    return ((const int*)mp)[i] != 0;
}

// ================= kernel 1: prep (init + count + scan + scatter) =================
__global__ void __launch_bounds__(NTHRP)
k_prep(const float* __restrict__ pts, const void* __restrict__ mask) {
    const int tid = threadIdx.x;
    const int bid = blockIdx.x;
    const int gid = bid * NTHRP + tid;

    // phase 0: zero state
    for (int i = gid; i < BB * GC; i += NBLKP * NTHRP) g_cnt[i] = 0;
    if (gid == 0) {
        for (int b = 0; b < BB; b++)
            for (int c = 0; c < 4; c++) g_cacc[b][c] = 0.0;
        g_mtype = 0;
        const float R = 0.02f;
        float t = __fmul_rn(R, R);
        while (__fsqrt_rn(t) >= R) t = __uint_as_float(__float_as_uint(t) - 1u);
        for (;;) {
            float nt = __uint_as_float(__float_as_uint(t) + 1u);
            if (__fsqrt_rn(nt) < R) t = nt; else break;
        }
        g_T = t;
    }
    gridbar();

    // phase 1: cell counts + mask dtype detect
    {
        bool act = gid < NPT;
        unsigned char mb = 0;
        if (act) {
            float x = pts[gid * 3 + 0], y = pts[gid * 3 + 1], z = pts[gid * 3 + 2];
            mb = ((const unsigned char*)mask)[gid];
            atomicAdd(&g_cnt[(gid >> 13) * GC + cell_of(x, y, z)], 1);
        }
        int r = gid & 3;
        unsigned m1 = __ballot_sync(0xFFFFFFFFu, act && (r == 1) && mb);
        unsigned m2 = __ballot_sync(0xFFFFFFFFu, act && (r >= 2) && mb);
        if ((tid & 31) == 0 && (m1 | m2))
            atomicOr(&g_mtype, (m1 ? 1 : 0) | (m2 ? 2 : 0));
    }
    gridbar();

    // phase 2: per-batch exclusive scan over GC=8000 cells (blocks 0,1)
    if (bid < BB) {
        __shared__ int part[NTHRP];
        int base = bid * GC + tid * 32;
        int loc[32]; int s = 0;
#pragma unroll
        for (int k = 0; k < 32; k++) {
            loc[k] = s;
            if (tid * 32 + k < GC) s += g_cnt[base + k];
        }
        part[tid] = s;
        __syncthreads();
        for (int d = 1; d < NTHRP; d <<= 1) {
            int v = (tid >= d) ? part[tid - d] : 0;
            __syncthreads();
            part[tid] += v;
            __syncthreads();
        }
        int off = part[tid] - s;
#pragma unroll
        for (int k = 0; k < 32; k++) {
            if (tid * 32 + k < GC) {
                int st = off + loc[k];
                g_range[base + k] = make_int2(st, st + g_cnt[base + k]);
                g_cur[base + k]   = st;
            }
        }
    }
    gridbar();

    // phase 3: scatter + masked centroid
    if (gid < NPT) {
        int mt = g_mtype;
        float x = pts[gid * 3 + 0], y = pts[gid * 3 + 1], z = pts[gid * 3 + 2];
        float sq = __fadd_rn(__fadd_rn(__fmul_rn(x, x), __fmul_rn(y, y)), __fmul_rn(z, z));
        int b = gid >> 13;
        int cell = b * GC + cell_of(x, y, z);
        bool mk = read_mask(mask, gid, mt);
        float wv = mk ? __uint_as_float(__float_as_uint(sq) | 0x80000000u) : sq;
        int pos = atomicAdd(&g_cur[cell], 1);
        int dst = b * NN + pos;
        g_sp4[dst]  = make_float4(x, y, z, wv);
        g_sidx[dst] = gid;
        double vx = mk ? (double)x : 0.0, vy = mk ? (double)y : 0.0;
        double vz = mk ? (double)z : 0.0, vc = mk ? 1.0 : 0.0;
#pragma unroll
        for (int o = 16; o > 0; o >>= 1) {
            vx += __shfl_down_sync(0xFFFFFFFFu, vx, o);
            vy += __shfl_down_sync(0xFFFFFFFFu, vy, o);
            vz += __shfl_down_sync(0xFFFFFFFFu, vz, o);
            vc += __shfl_down_sync(0xFFFFFFFFu, vc, o);
        }
        if ((tid & 31) == 0) {
            atomicAdd(&g_cacc[b][0], vx);
            atomicAdd(&g_cacc[b][1], vy);
            atomicAdd(&g_cacc[b][2], vz);
            atomicAdd(&g_cacc[b][3], vc);
        }
    }
}

// ---------------- analytic eigenvalues of symmetric 3x3 (fp64) ----------------
__device__ __forceinline__ float curv_from_cov(float c00, float c01, float c02,
                                               float c11, float c12, float c22) {
    double a00 = c00, a01 = c01, a02 = c02, a11 = c11, a12 = c12, a22 = c22;
    double p1 = a01 * a01 + a02 * a02 + a12 * a12;
    double q  = (a00 + a11 + a22) / 3.0;
    double d0 = a00 - q, d1 = a11 - q, d2v = a22 - q;
    double p2 = d0 * d0 + d1 * d1 + d2v * d2v + 2.0 * p1;
    double emin, emax;
    if (!(p2 > 0.0)) { emin = q; emax = q; }
    else {
        double p = sqrt(p2 / 6.0);
        double ip = 1.0 / p;
        double b00 = d0 * ip, b11 = d1 * ip, b22 = d2v * ip;
        double b01 = a01 * ip, b02 = a02 * ip, b12 = a12 * ip;
        double detB = b00 * (b11 * b22 - b12 * b12)
                    - b01 * (b01 * b22 - b12 * b02)
                    + b02 * (b01 * b12 - b11 * b02);
        double r = 0.5 * detB;
        r = fmin(1.0, fmax(-1.0, r));
        double phi = acos(r) / 3.0;
        emax = q + 2.0 * p * cos(phi);
        emin = q + 2.0 * p * cos(phi + 2.0943951023931953);
    }
    float e0 = (float)emin, e2 = (float)emax;
    return e0 / (e2 + 1e-8f);
}

// ================= kernel 2: 8-lane cooperative exact 10-NN + density =================
__global__ void __launch_bounds__(256) k_geom2() {
    const int gt = blockIdx.x * 256 + threadIdx.x;   // 131072 threads
    const int p  = gt >> 3;
    const int l8 = gt & 7;
    const int b  = p >> 13;
    const int s  = p & (NN - 1);
    const int boff  = b * NN;
    const int cbase = b * GC;
    const unsigned gmask = 0xFFu << ((threadIdx.x & 31) & ~7);

    float4 pi = g_sp4[boff + s];
    const float pix = pi.x, piy = pi.y, piz = pi.z, piw = fabsf(pi.w);
    const int orig  = g_sidx[boff + s];
    const float Tloc = g_T;

    const int cix = min(GRID - 1, max(0, (int)(pix * (float)GRID)));
    const int ciy = min(GRID - 1, max(0, (int)(piy * (float)GRID)));
    const int ciz = min(GRID - 1, max(0, (int)(piz * (float)GRID)));

    // per-point kNN radius estimate: ~22 expected neighbors, wall-clip aware
    float r_est = 0.075f;
#pragma unroll
    for (int it = 0; it < 2; it++) {
        float fx = (fminf(pix + r_est, 1.0f) - fmaxf(pix - r_est, 0.0f)) / (2.0f * r_est);
        float fy = (fminf(piy + r_est, 1.0f) - fmaxf(piy - r_est, 0.0f)) / (2.0f * r_est);
        float fz = (fminf(piz + r_est, 1.0f) - fmaxf(piz - r_est, 0.0f)) / (2.0f * r_est);
        r_est = cbrtf(6.4e-4f / fmaxf(fx * fy * fz, 0.125f));
    }
    const float t_est = r_est * r_est;
    const unsigned long long GATE_EST =
        ((unsigned long long)__float_as_uint(t_est) << 32) | 0xFFFFFFFFull;
    const unsigned long long GATE_INF = 0xFFFFFFFFFFFFFFFFull;

    unsigned long long best[KNN];
    int cnt;
    float c00, c01, c02, c11, c12, c22;
    unsigned long long d10key;

    for (int R = 2;; R++) {
        unsigned long long ginit = (R == 2) ? GATE_EST : GATE_INF;

        for (;;) {   // attempt loop (gate verify / retry)
#pragma unroll
            for (int k = 0; k < KNN; k++) best[k] = ginit;
            cnt = 0;
            int passes = 0;

            const int W = 2 * R + 1;
            const int nr = W * W;
            const int x0 = max(cix - R, 0), x1 = min(cix + R, GRID - 1);
            int qy = l8, qz = 0;
            while (qy >= W) { qy -= W; qz++; }

            for (int q = l8; q < nr; q += 8) {
                int zz = ciz + qz - R, yy = ciy + qy - R;
                if ((unsigned)zz < GRID && (unsigned)yy < GRID) {
                    int crow = cbase + (zz * GRID + yy) * GRID;
                    int jst = g_range[crow + x0].x;
                    int jen = g_range[crow + x1].y;
                    for (int j = jst; j < jen; ++j) {
                        float4 pj = g_sp4[boff + j];
                        float sqj = fabsf(pj.w);
                        float Tv  = (__float_as_uint(pj.w) & 0x80000000u)
                                    ? Tloc : __int_as_float(0xff800000);
                        float dot = fmaf(pix, pj.x, fmaf(piy, pj.y, piz * pj.z));
                        float d2  = fmaf(-2.0f, dot, piw + sqj);
                        if (d2 <= Tv) cnt++;
                        float d2c = fmaxf(d2, 0.0f);
                        if (d2c < t_est) passes++;
                        unsigned long long key =
                            ((unsigned long long)__float_as_uint(d2c) << 32) | (unsigned)j;
                        if (key < best[KNN - 1]) {
#pragma unroll
                            for (int k = 0; k < KNN; k++) {
                                if (key < best[k]) {
                                    unsigned long long tmp = best[k]; best[k] = key; key = tmp;
                                }
                            }
                        }
                    }
                }
                qy += 8;
                while (qy >= W) { qy -= W; qz++; }
            }

            if (ginit == GATE_INF) break;
            int pall = passes;
            pall += __shfl_xor_sync(gmask, pall, 1);
            pall += __shfl_xor_sync(gmask, pall, 2);
            pall += __shfl_xor_sync(gmask, pall, 4);
            if (pall >= KNN) break;
            ginit = GATE_INF;
        }

        // merge top-10 across the 8 lanes; owner pops + accumulates covariance
        c00 = c01 = c02 = c11 = c12 = c22 = 0.0f;
        d10key = GATE_INF;
#pragma unroll
        for (int round = 0; round < KNN; round++) {
            unsigned long long m = best[0];
            m = min(m, __shfl_xor_sync(gmask, m, 1));
            m = min(m, __shfl_xor_sync(gmask, m, 2));
            m = min(m, __shfl_xor_sync(gmask, m, 4));
            bool real = ((unsigned)(m & 0xFFFFFFFFull)) != 0xFFFFFFFFu;
            if (m == best[0] && real) {
                int j = (int)(unsigned)(m & 0xFFFFFFFFull);
                float4 q = g_sp4[boff + j];
                float dx = q.x - pix, dy = q.y - piy, dz = q.z - piz;
                c00 = fmaf(dx, dx, c00); c01 = fmaf(dx, dy, c01); c02 = fmaf(dx, dz, c02);
                c11 = fmaf(dy, dy, c11); c12 = fmaf(dy, dz, c12); c22 = fmaf(dz, dz, c22);
#pragma unroll
                for (int k = 0; k < KNN - 1; k++) best[k] = best[k + 1];
                best[KNN - 1] = GATE_INF;
            }
            d10key = m;
        }

        // exactness bound: scanned-box interior walls, epsilon-conservative for HCELL rounding
        float g = __int_as_float(0x7f800000);
        if (cix - R > 0)        g = fminf(g, pix - (float)(cix - R) * HCELL);
        if (cix + R < GRID - 1) g = fminf(g, (float)(cix + R + 1) * HCELL - pix);
        if (ciy - R > 0)        g = fminf(g, piy - (float)(ciy - R) * HCELL);
        if (ciy + R < GRID - 1) g = fminf(g, (float)(ciy + R + 1) * HCELL - piy);
        if (ciz - R > 0)        g = fminf(g, piz - (float)(ciz - R) * HCELL);
        if (ciz + R < GRID - 1) g = fminf(g, (float)(ciz + R + 1) * HCELL - piz);
        g -= 2e-6f;
        bool filled = ((unsigned)(d10key & 0xFFFFFFFFull)) != 0xFFFFFFFFu;
        float d10 = __uint_as_float((unsigned)(d10key >> 32));
        if (filled && d10 < g * g) break;
        if (R >= GRID) break;
    }

    // reduce density + covariance across the 8 lanes
#pragma unroll
    for (int o = 1; o < 8; o <<= 1) {
        cnt += __shfl_xor_sync(gmask, cnt, o);
        c00 += __shfl_xor_sync(gmask, c00, o);
        c01 += __shfl_xor_sync(gmask, c01, o);
        c02 += __shfl_xor_sync(gmask, c02, o);
        c11 += __shfl_xor_sync(gmask, c11, o);
        c12 += __shfl_xor_sync(gmask, c12, o);
        c22 += __shfl_xor_sync(gmask, c22, o);
    }

    if (l8 == 0) {
        c00 = __fdiv_rn(c00, 10.0f); c01 = __fdiv_rn(c01, 10.0f); c02 = __fdiv_rn(c02, 10.0f);
        c11 = __fdiv_rn(c11, 10.0f); c12 = __fdiv_rn(c12, 10.0f); c22 = __fdiv_rn(c22, 10.0f);
        float curv = curv_from_cov(c00, c01, c02, c11, c12, c22);

        double cm   = g_cacc[b][3];
        double cden = cm > 1.0 ? cm : 1.0;
        float cx = (float)(g_cacc[b][0] / cden);
        float cy = (float)(g_cacc[b][1] / cden);
        float cz = (float)(g_cacc[b][2] / cden);
        float rx = pix - cx, ry = piy - cy, rz = piz - cz;
        float distc = __fsqrt_rn(__fadd_rn(__fadd_rn(__fmul_rn(rx, rx), __fmul_rn(ry, ry)), __fmul_rn(rz, rz)));
        float horiz = __fsqrt_rn(__fadd_rn(__fmul_rn(rx, rx), __fmul_rn(ry, ry)));
        float rad   = atan2f(ry, rx);

        bool valid = cm > 0.0;
        g_geom[orig * 6 + 0] = valid ? distc : 0.0f;
        g_geom[orig * 6 + 1] = valid ? rz    : 0.0f;
        g_geom[orig * 6 + 2] = valid ? horiz : 0.0f;
        g_geom[orig * 6 + 3] = valid ? (float)cnt : 0.0f;
        g_geom[orig * 6 + 4] = valid ? curv  : 0.0f;
        g_geom[orig * 6 + 5] = valid ? rad   : 0.0f;
    }
}

// ================= kernel 3: fused 2-layer MLP (f32x2 FMA, 1024 threads) =================
__global__ void __launch_bounds__(NTM) k_mlp(const float* __restrict__ feat,
                                             const float* __restrict__ W1,
                                             const float* __restrict__ b1,
                                             const float* __restrict__ W2,
                                             const float* __restrict__ b2,
                                             float* __restrict__ out) {
    extern __shared__ float sm[];
    float* sW1 = sm;             // 70*128
    float* sB1 = sm + 8960;
    float* sW2 = sm + 9088;      // 128*128
    float* sB2 = sm + 25472;
    float* sX  = sm + 25600;     // 128*72
    float* sH  = sm + 34816;     // 128*132

    int tid = threadIdx.x;
    for (int i = tid; i < 8960;  i += NTM) sW1[i] = W1[i];
    for (int i = tid; i < 16384; i += NTM) sW2[i] = W2[i];
    if (tid < 128) { sB1[tid] = b1[tid]; sB2[tid] = b2[tid]; }

    int m0 = blockIdx.x * 128;
    for (int i = tid; i < 128 * 64; i += NTM) {
        int r = i >> 6, c = i & 63;
        sX[r * 72 + c] = feat[(m0 + r) * 64 + c];
    }
    if (tid < 128 * 6) {
        int r = tid / 6, c = tid % 6;
        sX[r * 72 + 64 + c] = g_geom[(m0 + r) * 6 + c];
    }
    __syncthreads();

    int cg = tid & 31;   // 32 col groups: cols cg*4 .. cg*4+3
    int rg = tid >> 5;   // 32 row groups (= warp id): rows rg*4 .. rg*4+3

    unsigned long long acc[4][2];
#pragma unroll
    for (int r = 0; r < 4; r++) { acc[r][0] = 0ull; acc[r][1] = 0ull; }

    for (int k = 0; k < 70; k++) {
        ulonglong2 w2 = *(const ulonglong2*)(sW1 + k * 128 + cg * 4);
#pragma unroll
        for (int r = 0; r < 4; r++) {
            unsigned long long xp = pack2(sX[(rg * 4 + r) * 72 + k]);   // warp-broadcast
            FMA2(acc[r][0], w2.x, xp);
            FMA2(acc[r][1], w2.y, xp);
        }
    }
    {
        float4 bv = *(const float4*)(sB1 + cg * 4);
#pragma unroll
        for (int r = 0; r < 4; r++) {
            float a0, a1, a2, a3;
            unpack2(acc[r][0], a0, a1);
            unpack2(acc[r][1], a2, a3);
            float4 h;
            h.x = fmaxf(a0 + bv.x, 0.0f);
            h.y = fmaxf(a1 + bv.y, 0.0f);
            h.z = fmaxf(a2 + bv.z, 0.0f);
            h.w = fmaxf(a3 + bv.w, 0.0f);
            *(float4*)(sH + (rg * 4 + r) * 132 + cg * 4) = h;
        }
    }
    __syncthreads();

#pragma unroll
    for (int r = 0; r < 4; r++) { acc[r][0] = 0ull; acc[r][1] = 0ull; }

    for (int k = 0; k < 128; k++) {
        ulonglong2 w2 = *(const ulonglong2*)(sW2 + k * 128 + cg * 4);
#pragma unroll
        for (int r = 0; r < 4; r++) {
            unsigned long long hp = pack2(sH[(rg * 4 + r) * 132 + k]);
            FMA2(acc[r][0], w2.x, hp);
            FMA2(acc[r][1], w2.y, hp);
        }
    }
    {
        float4 bv = *(const float4*)(sB2 + cg * 4);
#pragma unroll
        for (int r = 0; r < 4; r++) {
            float a0, a1, a2, a3;
            unpack2(acc[r][0], a0, a1);
            unpack2(acc[r][1], a2, a3);
            float4 o;
            o.x = fmaxf(a0 + bv.x, 0.0f);
            o.y = fmaxf(a1 + bv.y, 0.0f);
            o.z = fmaxf(a2 + bv.z, 0.0f);
            o.w = fmaxf(a3 + bv.w, 0.0f);
            *(float4*)(out + (size_t)(m0 + rg * 4 + r) * 128 + cg * 4) = o;
        }
    }
}

// ---------------- launch ----------------
extern "C" void kernel_launch(void* const* d_in, const int* in_sizes, int n_in,
                              void* d_out, int out_size) {
    const float* points = (const float*)d_in[0];
    const float* feat   = (const float*)d_in[1];
    const void*  mask   = d_in[2];
    const float* W1     = (const float*)d_in[3];
    const float* b1     = (const float*)d_in[4];
    const float* W2     = (const float*)d_in[5];
    const float* b2     = (const float*)d_in[6];
    float* out = (float*)d_out;

    cudaFuncSetAttribute(k_mlp, cudaFuncAttributeMaxDynamicSharedMemorySize, 212992);

    k_prep <<<NBLKP, NTHRP>>>(points, mask);
    k_geom2<<<(NPT * 8) / 256, 256>>>();
    k_mlp  <<<NPT / 128, NTM, 206848>>>(feat, W1, b1, W2, b2, out);
}

// round 10
// speedup vs baseline: 2.0622x; 1.1226x over previous
#include <cuda_runtime.h>
#include <math.h>

#define BB 2
#define NN 8192
#define NPT (BB*NN)
#define KNN 10
#define GRID 16
#define GC (GRID*GRID*GRID)
#define HCELL 0.0625f
#define NBLKP 128
#define NTHRP 256
#define NTM 1024
#define PEPS 1e-6f

// ---------------- device scratch ----------------
__device__ float4 g_sp4[NPT];        // sorted points (x,y,z, sq with sign bit = mask)
__device__ int    g_sidx[NPT];       // sorted -> original index
__device__ int    g_cnt[BB*GC];      // INVARIANT: zero at kernel entry (re-zeroed in scan)
__device__ int2   g_range[BB*GC];    // (start,end) within batch
__device__ int    g_cur[BB*GC];
__device__ double g_cacc[BB][4];     // masked centroid sums + count (zeroed in scan phase)
__device__ float  g_geom[NPT * 6];
__device__ int    g_mtype;           // monotone OR of same data -> stable across replays
__device__ float  g_T;
__device__ unsigned g_barcnt = 0;
__device__ unsigned g_sense  = 0;

// ---------------- grid barrier (128 co-resident blocks) ----------------
__device__ __forceinline__ void gridbar() {
    __syncthreads();
    if (threadIdx.x == 0) {
        __threadfence();
        unsigned gen = atomicAdd(&g_sense, 0u);
        if (atomicAdd(&g_barcnt, 1u) == NBLKP - 1) {
            g_barcnt = 0;
            __threadfence();
            atomicAdd(&g_sense, 1u);
        } else {
            while (atomicAdd(&g_sense, 0u) == gen) {}
        }
        __threadfence();
    }
    __syncthreads();
}

// ---------------- f32x2 helpers ----------------
#define FMA2(d, a, b) asm("fma.rn.f32x2 %0, %1, %2, %3;" : "=l"(d) : "l"(a), "l"(b), "l"(d))
__device__ __forceinline__ unsigned long long pack2(float v) {
    unsigned long long r; unsigned u = __float_as_uint(v);
    asm("mov.b64 %0, {%1, %1};" : "=l"(r) : "r"(u));
    return r;
}
__device__ __forceinline__ void unpack2(unsigned long long v, float& lo, float& hi) {
    unsigned a, b;
    asm("mov.b64 {%0, %1}, %2;" : "=r"(a), "=r"(b) : "l"(v));
    lo = __uint_as_float(a); hi = __uint_as_float(b);
}

__device__ __forceinline__ int cell_of(float x, float y, float z) {
    int cx = min(GRID - 1, max(0, (int)(x * (float)GRID)));
    int cy = min(GRID - 1, max(0, (int)(y * (float)GRID)));
    int cz = min(GRID - 1, max(0, (int)(z * (float)GRID)));
    return (cz * GRID + cy) * GRID + cx;
}

__device__ __forceinline__ bool read_mask(const void* mp, int i, int mt) {
    if (mt & 1) return ((const unsigned char*)mp)[i] != 0;
    if (mt & 2) return ((const float*)mp)[i] != 0.0f;
    return ((const int*)mp)[i] != 0;
}

// ================= kernel 1: prep (count + scan + scatter, 2 gridbars) =================
__global__ void __launch_bounds__(NTHRP)
k_prep(const float* __restrict__ pts, const void* __restrict__ mask) {
    const int tid = threadIdx.x;
    const int bid = blockIdx.x;
    const int gid = bid * NTHRP + tid;

    // phase 1: cell counts + mask dtype detect (g_cnt is zero on entry by invariant)
    {
        bool act = gid < NPT;
        unsigned char mb = 0;
        if (act) {
            float x = pts[gid * 3 + 0], y = pts[gid * 3 + 1], z = pts[gid * 3 + 2];
            mb = ((const unsigned char*)mask)[gid];
            atomicAdd(&g_cnt[(gid >> 13) * GC + cell_of(x, y, z)], 1);
        }
        int r = gid & 3;
        unsigned m1 = __ballot_sync(0xFFFFFFFFu, act && (r == 1) && mb);
        unsigned m2 = __ballot_sync(0xFFFFFFFFu, act && (r >= 2) && mb);
        if ((tid & 31) == 0 && (m1 | m2))
            atomicOr(&g_mtype, (m1 ? 1 : 0) | (m2 ? 2 : 0));
    }
    gridbar();

    // phase 2: per-batch exclusive scan (blocks 0,1) + restore g_cnt invariant + g_cacc/g_T
    if (bid < BB) {
        __shared__ int part[NTHRP];
        int base = bid * GC + tid * 16;
        int loc[16]; int s = 0;
#pragma unroll
        for (int k = 0; k < 16; k++) { loc[k] = s; s += g_cnt[base + k]; }
        part[tid] = s;
        __syncthreads();
        for (int d = 1; d < NTHRP; d <<= 1) {
            int v = (tid >= d) ? part[tid - d] : 0;
            __syncthreads();
            part[tid] += v;
            __syncthreads();
        }
        int off = part[tid] - s;
#pragma unroll
        for (int k = 0; k < 16; k++) {
            int st = off + loc[k];
            int ln = g_cnt[base + k];
            g_range[base + k] = make_int2(st, st + ln);
            g_cur[base + k]   = st;
            g_cnt[base + k]   = 0;                 // restore invariant
        }
        if (gid == 0) {
            for (int b = 0; b < BB; b++)
                for (int c = 0; c < 4; c++) g_cacc[b][c] = 0.0;
            const float R = 0.02f;
            float t = __fmul_rn(R, R);
            while (__fsqrt_rn(t) >= R) t = __uint_as_float(__float_as_uint(t) - 1u);
            for (;;) {
                float nt = __uint_as_float(__float_as_uint(t) + 1u);
                if (__fsqrt_rn(nt) < R) t = nt; else break;
            }
            g_T = t;
        }
    }
    gridbar();

    // phase 3: scatter + masked centroid
    if (gid < NPT) {
        int mt = g_mtype;
        float x = pts[gid * 3 + 0], y = pts[gid * 3 + 1], z = pts[gid * 3 + 2];
        float sq = __fadd_rn(__fadd_rn(__fmul_rn(x, x), __fmul_rn(y, y)), __fmul_rn(z, z));
        int b = gid >> 13;
        int cell = b * GC + cell_of(x, y, z);
        bool mk = read_mask(mask, gid, mt);
        float wv = mk ? __uint_as_float(__float_as_uint(sq) | 0x80000000u) : sq;
        int pos = atomicAdd(&g_cur[cell], 1);
        int dst = b * NN + pos;
        g_sp4[dst]  = make_float4(x, y, z, wv);
        g_sidx[dst] = gid;
        double vx = mk ? (double)x : 0.0, vy = mk ? (double)y : 0.0;
        double vz = mk ? (double)z : 0.0, vc = mk ? 1.0 : 0.0;
#pragma unroll
        for (int o = 16; o > 0; o >>= 1) {
            vx += __shfl_down_sync(0xFFFFFFFFu, vx, o);
            vy += __shfl_down_sync(0xFFFFFFFFu, vy, o);
            vz += __shfl_down_sync(0xFFFFFFFFu, vz, o);
            vc += __shfl_down_sync(0xFFFFFFFFu, vc, o);
        }
        if ((tid & 31) == 0) {
            atomicAdd(&g_cacc[b][0], vx);
            atomicAdd(&g_cacc[b][1], vy);
            atomicAdd(&g_cacc[b][2], vz);
            atomicAdd(&g_cacc[b][3], vc);
        }
    }
}

// ---------------- analytic eigenvalues of symmetric 3x3 (fp64) ----------------
__device__ __forceinline__ float curv_from_cov(float c00, float c01, float c02,
                                               float c11, float c12, float c22) {
    double a00 = c00, a01 = c01, a02 = c02, a11 = c11, a12 = c12, a22 = c22;
    double p1 = a01 * a01 + a02 * a02 + a12 * a12;
    double q  = (a00 + a11 + a22) / 3.0;
    double d0 = a00 - q, d1 = a11 - q, d2v = a22 - q;
    double p2 = d0 * d0 + d1 * d1 + d2v * d2v + 2.0 * p1;
    double emin, emax;
    if (!(p2 > 0.0)) { emin = q; emax = q; }
    else {
        double p = sqrt(p2 / 6.0);
        double ip = 1.0 / p;
        double b00 = d0 * ip, b11 = d1 * ip, b22 = d2v * ip;
        double b01 = a01 * ip, b02 = a02 * ip, b12 = a12 * ip;
        double detB = b00 * (b11 * b22 - b12 * b12)
                    - b01 * (b01 * b22 - b12 * b02)
                    + b02 * (b01 * b12 - b11 * b02);
        double r = 0.5 * detB;
        r = fmin(1.0, fmax(-1.0, r));
        double phi = acos(r) / 3.0;
        emax = q + 2.0 * p * cos(phi);
        emin = q + 2.0 * p * cos(phi + 2.0943951023931953);
    }
    float e0 = (float)emin, e2 = (float)emax;
    return e0 / (e2 + 1e-8f);
}

// ================= kernel 2: 8-lane cooperative exact 10-NN + density =================
__global__ void __launch_bounds__(256) k_geom2() {
    const int gt = blockIdx.x * 256 + threadIdx.x;   // 131072 threads
    const int p  = gt >> 3;
    const int l8 = gt & 7;
    const int b  = p >> 13;
    const int s  = p & (NN - 1);
    const int boff  = b * NN;
    const int cbase = b * GC;
    const unsigned gmask = 0xFFu << ((threadIdx.x & 31) & ~7);

    float4 pi = g_sp4[boff + s];
    const float pix = pi.x, piy = pi.y, piz = pi.z, piw = fabsf(pi.w);
    const int orig  = g_sidx[boff + s];
    const float Tloc = g_T;

    const int cix = min(GRID - 1, max(0, (int)(pix * (float)GRID)));
    const int ciy = min(GRID - 1, max(0, (int)(piy * (float)GRID)));
    const int ciz = min(GRID - 1, max(0, (int)(piz * (float)GRID)));

    // per-point kNN radius estimate: ~22 expected neighbors, wall-clip aware
    float r_est = 0.075f;
#pragma unroll
    for (int it = 0; it < 2; it++) {
        float fx = (fminf(pix + r_est, 1.0f) - fmaxf(pix - r_est, 0.0f)) / (2.0f * r_est);
        float fy = (fminf(piy + r_est, 1.0f) - fmaxf(piy - r_est, 0.0f)) / (2.0f * r_est);
        float fz = (fminf(piz + r_est, 1.0f) - fmaxf(piz - r_est, 0.0f)) / (2.0f * r_est);
        r_est = cbrtf(6.4e-4f / fmaxf(fx * fy * fz, 0.125f));
    }
    const float t_est = r_est * r_est;
    const unsigned long long GATE_EST =
        ((unsigned long long)__float_as_uint(t_est) << 32) | 0xFFFFFFFFull;
    const unsigned long long GATE_INF = 0xFFFFFFFFFFFFFFFFull;

    unsigned long long best[KNN];
    int cnt;
    float c00, c01, c02, c11, c12, c22;
    unsigned long long d10key;

    for (int R = 2;; R++) {
        unsigned long long ginit = (R == 2) ? GATE_EST : GATE_INF;

        for (;;) {   // attempt loop (gate verify / retry)
#pragma unroll
            for (int k = 0; k < KNN; k++) best[k] = ginit;
            cnt = 0;
            int passes = 0;
            const bool gated = (ginit != GATE_INF);

            const int W = 2 * R + 1;
            const int nr = W * W;
            const int x0 = max(cix - R, 0), x1 = min(cix + R, GRID - 1);
            int qy = l8, qz = 0;
            while (qy >= W) { qy -= W; qz++; }

            for (int q = l8; q < nr; q += 8) {
                int zz = ciz + qz - R, yy = ciy + qy - R;
                if ((unsigned)zz < GRID && (unsigned)yy < GRID) {
                    int crow = cbase + (zz * GRID + yy) * GRID;
                    int jst, jen;
                    bool skip = false;
                    if (gated) {
                        // exact min-distance^2 from pi to this row of cells
                        float zlo = (float)zz * HCELL, zhi = zlo + HCELL;
                        float ylo = (float)yy * HCELL, yhi = ylo + HCELL;
                        float dzl = fmaxf(0.0f, fmaxf(zlo - piz, piz - zhi));
                        float dyl = fmaxf(0.0f, fmaxf(ylo - piy, piy - yhi));
                        float rb2 = dzl * dzl + dyl * dyl;
                        if (rb2 > t_est + PEPS) {
                            skip = true;
                            jst = 0; jen = 0;
                        } else {
                            float xr = sqrtf(t_est + PEPS - rb2);
                            int xlo = (int)((pix - xr) * (float)GRID);
                            int xhi = (int)((pix + xr) * (float)GRID);
                            int xa = max(x0, xlo), xb = min(x1, xhi);
                            jst = g_range[crow + xa].x;
                            jen = g_range[crow + xb].y;
                        }
                    } else {
                        jst = g_range[crow + x0].x;
                        jen = g_range[crow + x1].y;
                    }
                    if (!skip) {
                        for (int j = jst; j < jen; ++j) {
                            float4 pj = g_sp4[boff + j];
                            float sqj = fabsf(pj.w);
                            float Tv  = (__float_as_uint(pj.w) & 0x80000000u)
                                        ? Tloc : __int_as_float(0xff800000);
                            float dot = fmaf(pix, pj.x, fmaf(piy, pj.y, piz * pj.z));
                            float d2  = fmaf(-2.0f, dot, piw + sqj);
                            if (d2 <= Tv) cnt++;
                            float d2c = fmaxf(d2, 0.0f);
                            if (d2c < t_est) passes++;
                            unsigned long long key =
                                ((unsigned long long)__float_as_uint(d2c) << 32) | (unsigned)j;
                            if (key < best[KNN - 1]) {
#pragma unroll
                                for (int k = 0; k < KNN; k++) {
                                    if (key < best[k]) {
                                        unsigned long long tmp = best[k]; best[k] = key; key = tmp;
                                    }
                                }
                            }
                        }
                    }
                }
                qy += 8;
                while (qy >= W) { qy -= W; qz++; }
            }

            if (!gated) break;
            int pall = passes;
            pall += __shfl_xor_sync(gmask, pall, 1);
            pall += __shfl_xor_sync(gmask, pall, 2);
            pall += __shfl_xor_sync(gmask, pall, 4);
            if (pall >= KNN) break;
            ginit = GATE_INF;
        }

        // merge top-10 across the 8 lanes; owner pops + accumulates covariance
        c00 = c01 = c02 = c11 = c12 = c22 = 0.0f;
        d10key = GATE_INF;
#pragma unroll
        for (int round = 0; round < KNN; round++) {
            unsigned long long m = best[0];
            m = min(m, __shfl_xor_sync(gmask, m, 1));
            m = min(m, __shfl_xor_sync(gmask, m, 2));
            m = min(m, __shfl_xor_sync(gmask, m, 4));
            bool real = ((unsigned)(m & 0xFFFFFFFFull)) != 0xFFFFFFFFu;
            if (m == best[0] && real) {
                int j = (int)(unsigned)(m & 0xFFFFFFFFull);
                float4 q = g_sp4[boff + j];
                float dx = q.x - pix, dy = q.y - piy, dz = q.z - piz;
                c00 = fmaf(dx, dx, c00); c01 = fmaf(dx, dy, c01); c02 = fmaf(dx, dz, c02);
                c11 = fmaf(dy, dy, c11); c12 = fmaf(dy, dz, c12); c22 = fmaf(dz, dz, c22);
#pragma unroll
                for (int k = 0; k < KNN - 1; k++) best[k] = best[k + 1];
                best[KNN - 1] = GATE_INF;
            }
            d10key = m;
        }

        // exactness bound: 10th dist vs distance to scanned-box interior walls
        float g = __int_as_float(0x7f800000);
        if (cix - R > 0)        g = fminf(g, pix - (float)(cix - R) * HCELL);
        if (cix + R < GRID - 1) g = fminf(g, (float)(cix + R + 1) * HCELL - pix);
        if (ciy - R > 0)        g = fminf(g, piy - (float)(ciy - R) * HCELL);
        if (ciy + R < GRID - 1) g = fminf(g, (float)(ciy + R + 1) * HCELL - piy);
        if (ciz - R > 0)        g = fminf(g, piz - (float)(ciz - R) * HCELL);
        if (ciz + R < GRID - 1) g = fminf(g, (float)(ciz + R + 1) * HCELL - piz);
        bool filled = ((unsigned)(d10key & 0xFFFFFFFFull)) != 0xFFFFFFFFu;
        float d10 = __uint_as_float((unsigned)(d10key >> 32));
        if (filled && d10 < g * g) break;
        if (R >= GRID) break;
    }

    // reduce density + covariance across the 8 lanes
#pragma unroll
    for (int o = 1; o < 8; o <<= 1) {
        cnt += __shfl_xor_sync(gmask, cnt, o);
        c00 += __shfl_xor_sync(gmask, c00, o);
        c01 += __shfl_xor_sync(gmask, c01, o);
        c02 += __shfl_xor_sync(gmask, c02, o);
        c11 += __shfl_xor_sync(gmask, c11, o);
        c12 += __shfl_xor_sync(gmask, c12, o);
        c22 += __shfl_xor_sync(gmask, c22, o);
    }

    if (l8 == 0) {
        c00 = __fdiv_rn(c00, 10.0f); c01 = __fdiv_rn(c01, 10.0f); c02 = __fdiv_rn(c02, 10.0f);
        c11 = __fdiv_rn(c11, 10.0f); c12 = __fdiv_rn(c12, 10.0f); c22 = __fdiv_rn(c22, 10.0f);
        float curv = curv_from_cov(c00, c01, c02, c11, c12, c22);

        double cm   = g_cacc[b][3];
        double cden = cm > 1.0 ? cm : 1.0;
        float cx = (float)(g_cacc[b][0] / cden);
        float cy = (float)(g_cacc[b][1] / cden);
        float cz = (float)(g_cacc[b][2] / cden);
        float rx = pix - cx, ry = piy - cy, rz = piz - cz;
        float distc = __fsqrt_rn(__fadd_rn(__fadd_rn(__fmul_rn(rx, rx), __fmul_rn(ry, ry)), __fmul_rn(rz, rz)));
        float horiz = __fsqrt_rn(__fadd_rn(__fmul_rn(rx, rx), __fmul_rn(ry, ry)));
        float rad   = atan2f(ry, rx);

        bool valid = cm > 0.0;
        g_geom[orig * 6 + 0] = valid ? distc : 0.0f;
        g_geom[orig * 6 + 1] = valid ? rz    : 0.0f;
        g_geom[orig * 6 + 2] = valid ? horiz : 0.0f;
        g_geom[orig * 6 + 3] = valid ? (float)cnt : 0.0f;
        g_geom[orig * 6 + 4] = valid ? curv  : 0.0f;
        g_geom[orig * 6 + 5] = valid ? rad   : 0.0f;
    }
}

// ================= kernel 3: fused 2-layer MLP (f32x2 FMA, 1024 threads) =================
__global__ void __launch_bounds__(NTM) k_mlp(const float* __restrict__ feat,
                                             const float* __restrict__ W1,
                                             const float* __restrict__ b1,
                                             const float* __restrict__ W2,
                                             const float* __restrict__ b2,
                                             float* __restrict__ out) {
    extern __shared__ float sm[];
    float* sW1 = sm;             // 70*128
    float* sB1 = sm + 8960;
    float* sW2 = sm + 9088;      // 128*128
    float* sB2 = sm + 25472;
    float* sX  = sm + 25600;     // 128*72
    float* sH  = sm + 34816;     // 128*132

    int tid = threadIdx.x;
    for (int i = tid; i < 8960;  i += NTM) sW1[i] = W1[i];
    for (int i = tid; i < 16384; i += NTM) sW2[i] = W2[i];
    if (tid < 128) { sB1[tid] = b1[tid]; sB2[tid] = b2[tid]; }

    int m0 = blockIdx.x * 128;
    for (int i = tid; i < 128 * 64; i += NTM) {
        int r = i >> 6, c = i & 63;
        sX[r * 72 + c] = feat[(m0 + r) * 64 + c];
    }
    if (tid < 128 * 6) {
        int r = tid / 6, c = tid % 6;
        sX[r * 72 + 64 + c] = g_geom[(m0 + r) * 6 + c];
    }
    __syncthreads();

    int cg = tid & 31;   // 32 col groups: cols cg*4 .. cg*4+3
    int rg = tid >> 5;   // 32 row groups (= warp id): rows rg*4 .. rg*4+3

    unsigned long long acc[4][2];
#pragma unroll
    for (int r = 0; r < 4; r++) { acc[r][0] = 0ull; acc[r][1] = 0ull; }

    for (int k = 0; k < 70; k++) {
        ulonglong2 w2 = *(const ulonglong2*)(sW1 + k * 128 + cg * 4);
#pragma unroll
        for (int r = 0; r < 4; r++) {
            unsigned long long xp = pack2(sX[(rg * 4 + r) * 72 + k]);   // warp-broadcast
            FMA2(acc[r][0], w2.x, xp);
            FMA2(acc[r][1], w2.y, xp);
        }
    }
    {
        float4 bv = *(const float4*)(sB1 + cg * 4);
#pragma unroll
        for (int r = 0; r < 4; r++) {
            float a0, a1, a2, a3;
            unpack2(acc[r][0], a0, a1);
            unpack2(acc[r][1], a2, a3);
            float4 h;
            h.x = fmaxf(a0 + bv.x, 0.0f);
            h.y = fmaxf(a1 + bv.y, 0.0f);
            h.z = fmaxf(a2 + bv.z, 0.0f);
            h.w = fmaxf(a3 + bv.w, 0.0f);
            *(float4*)(sH + (rg * 4 + r) * 132 + cg * 4) = h;
        }
    }
    __syncthreads();

#pragma unroll
    for (int r = 0; r < 4; r++) { acc[r][0] = 0ull; acc[r][1] = 0ull; }

    for (int k = 0; k < 128; k++) {
        ulonglong2 w2 = *(const ulonglong2*)(sW2 + k * 128 + cg * 4);
#pragma unroll
        for (int r = 0; r < 4; r++) {
            unsigned long long hp = pack2(sH[(rg * 4 + r) * 132 + k]);
            FMA2(acc[r][0], w2.x, hp);
            FMA2(acc[r][1], w2.y, hp);
        }
    }
    {
        float4 bv = *(const float4*)(sB2 + cg * 4);
#pragma unroll
        for (int r = 0; r < 4; r++) {
            float a0, a1, a2, a3;
            unpack2(acc[r][0], a0, a1);
            unpack2(acc[r][1], a2, a3);
            float4 o;
            o.x = fmaxf(a0 + bv.x, 0.0f);
            o.y = fmaxf(a1 + bv.y, 0.0f);
            o.z = fmaxf(a2 + bv.z, 0.0f);
            o.w = fmaxf(a3 + bv.w, 0.0f);
            *(float4*)(out + (size_t)(m0 + rg * 4 + r) * 128 + cg * 4) = o;
        }
    }
}

// ---------------- launch ----------------
extern "C" void kernel_launch(void* const* d_in, const int* in_sizes, int n_in,
                              void* d_out, int out_size) {
    const float* points = (const float*)d_in[0];
    const float* feat   = (const float*)d_in[1];
    const void*  mask   = d_in[2];
    const float* W1     = (const float*)d_in[3];
    const float* b1     = (const float*)d_in[4];
    const float* W2     = (const float*)d_in[5];
    const float* b2     = (const float*)d_in[6];
    float* out = (float*)d_out;

    cudaFuncSetAttribute(k_mlp, cudaFuncAttributeMaxDynamicSharedMemorySize, 212992);

    k_prep <<<NBLKP, NTHRP>>>(points, mask);
    k_geom2<<<(NPT * 8) / 256, 256>>>();
    k_mlp  <<<NPT / 128, NTM, 206848>>>(feat, W1, b1, W2, b2, out);
}

// round 11
// speedup vs baseline: 2.0989x; 1.0178x over previous
#include <cuda_runtime.h>
#include <math.h>

#define BB 2
#define NN 8192
#define NPT (BB*NN)
#define KNN 10
#define GRID 16
#define GC (GRID*GRID*GRID)
#define HCELL 0.0625f
#define NBLKP 128
#define NTHRP 256
#define NTM 1024
#define PEPS 1e-6f

// ---------------- device scratch ----------------
__device__ float4 g_sp4[NPT];        // sorted points (x,y,z, sq with sign bit = mask)
__device__ int    g_sidx[NPT];       // sorted -> original index
__device__ int    g_cnt[BB*GC];      // INVARIANT: zero at kernel entry (re-zeroed in scan)
__device__ int2   g_range[BB*GC];    // (start,end) within batch
__device__ int    g_cur[BB*GC];
__device__ double g_cacc[BB][4];     // masked centroid sums + count (zeroed in scan phase)
__device__ float  g_geom[NPT * 6];
__device__ int    g_mtype;           // monotone OR of same data -> stable across replays
__device__ float  g_T;
__device__ unsigned g_barcnt = 0;
__device__ unsigned g_sense  = 0;

// ---------------- grid barrier (128 co-resident blocks) ----------------
__device__ __forceinline__ void gridbar() {
    __syncthreads();
    if (threadIdx.x == 0) {
        __threadfence();
        unsigned gen = atomicAdd(&g_sense, 0u);
        if (atomicAdd(&g_barcnt, 1u) == NBLKP - 1) {
            g_barcnt = 0;
            __threadfence();
            atomicAdd(&g_sense, 1u);
        } else {
            while (atomicAdd(&g_sense, 0u) == gen) {}
        }
        __threadfence();
    }
    __syncthreads();
}

// ---------------- f32x2 helpers ----------------
#define FMA2(d, a, b) asm("fma.rn.f32x2 %0, %1, %2, %3;" : "=l"(d) : "l"(a), "l"(b), "l"(d))
__device__ __forceinline__ unsigned long long pack2(float v) {
    unsigned long long r; unsigned u = __float_as_uint(v);
    asm("mov.b64 %0, {%1, %1};" : "=l"(r) : "r"(u));
    return r;
}
__device__ __forceinline__ void unpack2(unsigned long long v, float& lo, float& hi) {
    unsigned a, b;
    asm("mov.b64 {%0, %1}, %2;" : "=r"(a), "=r"(b) : "l"(v));
    lo = __uint_as_float(a); hi = __uint_as_float(b);
}

__device__ __forceinline__ int cell_of(float x, float y, float z) {
    int cx = min(GRID - 1, max(0, (int)(x * (float)GRID)));
    int cy = min(GRID - 1, max(0, (int)(y * (float)GRID)));
    int cz = min(GRID - 1, max(0, (int)(z * (float)GRID)));
    return (cz * GRID + cy) * GRID + cx;
}

__device__ __forceinline__ bool read_mask(const void* mp, int i, int mt) {
    if (mt & 1) return ((const unsigned char*)mp)[i] != 0;
    if (mt & 2) return ((const float*)mp)[i] != 0.0f;
    return ((const int*)mp)[i] != 0;
}

// ================= kernel 1: prep (count + scan + scatter, 2 gridbars) =================
__global__ void __launch_bounds__(NTHRP)
k_prep(const float* __restrict__ pts, const void* __restrict__ mask) {
    const int tid = threadIdx.x;
    const int bid = blockIdx.x;
    const int gid = bid * NTHRP + tid;

    // phase 1: cell counts + mask dtype detect (g_cnt is zero on entry by invariant)
    {
        bool act = gid < NPT;
        unsigned char mb = 0;
        if (act) {
            float x = pts[gid * 3 + 0], y = pts[gid * 3 + 1], z = pts[gid * 3 + 2];
            mb = ((const unsigned char*)mask)[gid];
            atomicAdd(&g_cnt[(gid >> 13) * GC + cell_of(x, y, z)], 1);
        }
        int r = gid & 3;
        unsigned m1 = __ballot_sync(0xFFFFFFFFu, act && (r == 1) && mb);
        unsigned m2 = __ballot_sync(0xFFFFFFFFu, act && (r >= 2) && mb);
        if ((tid & 31) == 0 && (m1 | m2))
            atomicOr(&g_mtype, (m1 ? 1 : 0) | (m2 ? 2 : 0));
    }
    gridbar();

    // phase 2: per-batch exclusive scan (blocks 0,1) + restore g_cnt invariant + g_cacc/g_T
    if (bid < BB) {
        __shared__ int part[NTHRP];
        int base = bid * GC + tid * 16;
        int loc[16]; int s = 0;
#pragma unroll
        for (int k = 0; k < 16; k++) { loc[k] = s; s += g_cnt[base + k]; }
        part[tid] = s;
        __syncthreads();
        for (int d = 1; d < NTHRP; d <<= 1) {
            int v = (tid >= d) ? part[tid - d] : 0;
            __syncthreads();
            part[tid] += v;
            __syncthreads();
        }
        int off = part[tid] - s;
#pragma unroll
        for (int k = 0; k < 16; k++) {
            int st = off + loc[k];
            int ln = g_cnt[base + k];
            g_range[base + k] = make_int2(st, st + ln);
            g_cur[base + k]   = st;
            g_cnt[base + k]   = 0;                 // restore invariant
        }
        if (gid == 0) {
            for (int b = 0; b < BB; b++)
                for (int c = 0; c < 4; c++) g_cacc[b][c] = 0.0;
            const float R = 0.02f;
            float t = __fmul_rn(R, R);
            while (__fsqrt_rn(t) >= R) t = __uint_as_float(__float_as_uint(t) - 1u);
            for (;;) {
                float nt = __uint_as_float(__float_as_uint(t) + 1u);
                if (__fsqrt_rn(nt) < R) t = nt; else break;
            }
            g_T = t;
        }
    }
    gridbar();

    // phase 3: scatter + masked centroid
    if (gid < NPT) {
        int mt = g_mtype;
        float x = pts[gid * 3 + 0], y = pts[gid * 3 + 1], z = pts[gid * 3 + 2];
        float sq = __fadd_rn(__fadd_rn(__fmul_rn(x, x), __fmul_rn(y, y)), __fmul_rn(z, z));
        int b = gid >> 13;
        int cell = b * GC + cell_of(x, y, z);
        bool mk = read_mask(mask, gid, mt);
        float wv = mk ? __uint_as_float(__float_as_uint(sq) | 0x80000000u) : sq;
        int pos = atomicAdd(&g_cur[cell], 1);
        int dst = b * NN + pos;
        g_sp4[dst]  = make_float4(x, y, z, wv);
        g_sidx[dst] = gid;
        double vx = mk ? (double)x : 0.0, vy = mk ? (double)y : 0.0;
        double vz = mk ? (double)z : 0.0, vc = mk ? 1.0 : 0.0;
#pragma unroll
        for (int o = 16; o > 0; o >>= 1) {
            vx += __shfl_down_sync(0xFFFFFFFFu, vx, o);
            vy += __shfl_down_sync(0xFFFFFFFFu, vy, o);
            vz += __shfl_down_sync(0xFFFFFFFFu, vz, o);
            vc += __shfl_down_sync(0xFFFFFFFFu, vc, o);
        }
        if ((tid & 31) == 0) {
            atomicAdd(&g_cacc[b][0], vx);
            atomicAdd(&g_cacc[b][1], vy);
            atomicAdd(&g_cacc[b][2], vz);
            atomicAdd(&g_cacc[b][3], vc);
        }
    }
}

// ---------------- analytic eigenvalues of symmetric 3x3 (fp64) ----------------
__device__ __forceinline__ float curv_from_cov(float c00, float c01, float c02,
                                               float c11, float c12, float c22) {
    double a00 = c00, a01 = c01, a02 = c02, a11 = c11, a12 = c12, a22 = c22;
    double p1 = a01 * a01 + a02 * a02 + a12 * a12;
    double q  = (a00 + a11 + a22) / 3.0;
    double d0 = a00 - q, d1 = a11 - q, d2v = a22 - q;
    double p2 = d0 * d0 + d1 * d1 + d2v * d2v + 2.0 * p1;
    double emin, emax;
    if (!(p2 > 0.0)) { emin = q; emax = q; }
    else {
        double p = sqrt(p2 / 6.0);
        double ip = 1.0 / p;
        double b00 = d0 * ip, b11 = d1 * ip, b22 = d2v * ip;
        double b01 = a01 * ip, b02 = a02 * ip, b12 = a12 * ip;
        double detB = b00 * (b11 * b22 - b12 * b12)
                    - b01 * (b01 * b22 - b12 * b02)
                    + b02 * (b01 * b12 - b11 * b02);
        double r = 0.5 * detB;
        r = fmin(1.0, fmax(-1.0, r));
        double phi = acos(r) / 3.0;
        emax = q + 2.0 * p * cos(phi);
        emin = q + 2.0 * p * cos(phi + 2.0943951023931953);
    }
    float e0 = (float)emin, e2 = (float)emax;
    return e0 / (e2 + 1e-8f);
}

// ================= kernel 2: 8-lane cooperative exact 10-NN + density =================
__global__ void __launch_bounds__(256) k_geom2() {
    const int gt = blockIdx.x * 256 + threadIdx.x;   // 131072 threads
    const int p  = gt >> 3;
    const int l8 = gt & 7;
    const int b  = p >> 13;
    const int s  = p & (NN - 1);
    const int boff  = b * NN;
    const int cbase = b * GC;
    const unsigned gmask = 0xFFu << ((threadIdx.x & 31) & ~7);

    float4 pi = __ldg(&g_sp4[boff + s]);
    const float pix = pi.x, piy = pi.y, piz = pi.z, piw = fabsf(pi.w);
    const int orig  = g_sidx[boff + s];
    const float Tloc = g_T;

    const int cix = min(GRID - 1, max(0, (int)(pix * (float)GRID)));
    const int ciy = min(GRID - 1, max(0, (int)(piy * (float)GRID)));
    const int ciz = min(GRID - 1, max(0, (int)(piz * (float)GRID)));

    // per-point kNN radius estimate: ~22 expected neighbors, wall-clip aware
    float r_est = 0.075f;
#pragma unroll
    for (int it = 0; it < 2; it++) {
        float fx = (fminf(pix + r_est, 1.0f) - fmaxf(pix - r_est, 0.0f)) / (2.0f * r_est);
        float fy = (fminf(piy + r_est, 1.0f) - fmaxf(piy - r_est, 0.0f)) / (2.0f * r_est);
        float fz = (fminf(piz + r_est, 1.0f) - fmaxf(piz - r_est, 0.0f)) / (2.0f * r_est);
        r_est = cbrtf(6.4e-4f / fmaxf(fx * fy * fz, 0.125f));
    }
    const float t_est = r_est * r_est;
    const unsigned long long GATE_EST =
        ((unsigned long long)__float_as_uint(t_est) << 32) | 0xFFFFFFFFull;
    const unsigned long long GATE_INF = 0xFFFFFFFFFFFFFFFFull;

    unsigned long long best[KNN];
    int cnt;
    float c00, c01, c02, c11, c12, c22;
    unsigned long long d10key;

    for (int R = 2;; R++) {
        bool scanned = false;

        if (R == 2) {
            // ======== gated fast path: preloaded pruned row ranges (MLP=8) ========
#pragma unroll
            for (int k = 0; k < KNN; k++) best[k] = GATE_EST;
            cnt = 0;
            int passes = 0;

            const int x0 = max(cix - 2, 0), x1 = min(cix + 2, GRID - 1);
            int rjst[4], rjen[4];
#pragma unroll
            for (int i = 0; i < 4; i++) {
                rjst[i] = 0; rjen[i] = 0;
                int q = l8 + 8 * i;
                if (q < 25) {
                    int zz = ciz + q / 5 - 2, yy = ciy + q % 5 - 2;
                    if ((unsigned)zz < GRID && (unsigned)yy < GRID) {
                        float zlo = (float)zz * HCELL, zhi = zlo + HCELL;
                        float ylo = (float)yy * HCELL, yhi = ylo + HCELL;
                        float dzl = fmaxf(0.0f, fmaxf(zlo - piz, piz - zhi));
                        float dyl = fmaxf(0.0f, fmaxf(ylo - piy, piy - yhi));
                        float rb2 = dzl * dzl + dyl * dyl;
                        if (rb2 <= t_est + PEPS) {
                            float xr = sqrtf(t_est + PEPS - rb2);
                            int xlo = (int)((pix - xr) * (float)GRID);
                            int xhi = (int)((pix + xr) * (float)GRID);
                            int xa = max(x0, xlo), xb = min(x1, xhi);
                            int crow = cbase + (zz * GRID + yy) * GRID;
                            rjst[i] = __ldg(&g_range[crow + xa].x);
                            rjen[i] = __ldg(&g_range[crow + xb].y);
                        }
                    }
                }
            }
#pragma unroll
            for (int i = 0; i < 4; i++) {
#pragma unroll 2
                for (int j = rjst[i]; j < rjen[i]; ++j) {
                    float4 pj = __ldg(&g_sp4[boff + j]);
                    float sqj = fabsf(pj.w);
                    float Tv  = (__float_as_uint(pj.w) & 0x80000000u)
                                ? Tloc : __int_as_float(0xff800000);
                    float dot = fmaf(pix, pj.x, fmaf(piy, pj.y, piz * pj.z));
                    float d2  = fmaf(-2.0f, dot, piw + sqj);
                    if (d2 <= Tv) cnt++;
                    float d2c = fmaxf(d2, 0.0f);
                    if (d2c < t_est) passes++;
                    unsigned long long key =
                        ((unsigned long long)__float_as_uint(d2c) << 32) | (unsigned)j;
                    if (key < best[KNN - 1]) {
#pragma unroll
                        for (int k = 0; k < KNN; k++) {
                            if (key < best[k]) {
                                unsigned long long tmp = best[k]; best[k] = key; key = tmp;
                            }
                        }
                    }
                }
            }

            int pall = passes;
            pall += __shfl_xor_sync(gmask, pall, 1);
            pall += __shfl_xor_sync(gmask, pall, 2);
            pall += __shfl_xor_sync(gmask, pall, 4);
            if (pall >= KNN) scanned = true;   // gate verified: true top-10 captured
        }

        if (!scanned) {
            // ======== ungated generic scan at radius R ========
#pragma unroll
            for (int k = 0; k < KNN; k++) best[k] = GATE_INF;
            cnt = 0;

            const int W = 2 * R + 1;
            const int nr = W * W;
            const int x0 = max(cix - R, 0), x1 = min(cix + R, GRID - 1);
            int qy = l8, qz = 0;
            while (qy >= W) { qy -= W; qz++; }

            for (int q = l8; q < nr; q += 8) {
                int zz = ciz + qz - R, yy = ciy + qy - R;
                if ((unsigned)zz < GRID && (unsigned)yy < GRID) {
                    int crow = cbase + (zz * GRID + yy) * GRID;
                    int jst = __ldg(&g_range[crow + x0].x);
                    int jen = __ldg(&g_range[crow + x1].y);
                    for (int j = jst; j < jen; ++j) {
                        float4 pj = __ldg(&g_sp4[boff + j]);
                        float sqj = fabsf(pj.w);
                        float Tv  = (__float_as_uint(pj.w) & 0x80000000u)
                                    ? Tloc : __int_as_float(0xff800000);
                        float dot = fmaf(pix, pj.x, fmaf(piy, pj.y, piz * pj.z));
                        float d2  = fmaf(-2.0f, dot, piw + sqj);
                        if (d2 <= Tv) cnt++;
                        float d2c = fmaxf(d2, 0.0f);
                        unsigned long long key =
                            ((unsigned long long)__float_as_uint(d2c) << 32) | (unsigned)j;
                        if (key < best[KNN - 1]) {
#pragma unroll
                            for (int k = 0; k < KNN; k++) {
                                if (key < best[k]) {
                                    unsigned long long tmp = best[k]; best[k] = key; key = tmp;
                                }
                            }
                        }
                    }
                }
                qy += 8;
                while (qy >= W) { qy -= W; qz++; }
            }
        }

        // merge top-10 across the 8 lanes; owner pops + accumulates covariance
        c00 = c01 = c02 = c11 = c12 = c22 = 0.0f;
        d10key = GATE_INF;
#pragma unroll
        for (int round = 0; round < KNN; round++) {
            unsigned long long m = best[0];
            m = min(m, __shfl_xor_sync(gmask, m, 1));
            m = min(m, __shfl_xor_sync(gmask, m, 2));
            m = min(m, __shfl_xor_sync(gmask, m, 4));
            bool real = ((unsigned)(m & 0xFFFFFFFFull)) != 0xFFFFFFFFu;
            if (m == best[0] && real) {
                int j = (int)(unsigned)(m & 0xFFFFFFFFull);
                float4 q = __ldg(&g_sp4[boff + j]);
                float dx = q.x - pix, dy = q.y - piy, dz = q.z - piz;
                c00 = fmaf(dx, dx, c00); c01 = fmaf(dx, dy, c01); c02 = fmaf(dx, dz, c02);
                c11 = fmaf(dy, dy, c11); c12 = fmaf(dy, dz, c12); c22 = fmaf(dz, dz, c22);
#pragma unroll
                for (int k = 0; k < KNN - 1; k++) best[k] = best[k + 1];
                best[KNN - 1] = GATE_INF;
            }
            d10key = m;
        }

        // exactness bound: 10th dist vs distance to scanned-box interior walls
        float g = __int_as_float(0x7f800000);
        if (cix - R > 0)        g = fminf(g, pix - (float)(cix - R) * HCELL);
        if (cix + R < GRID - 1) g = fminf(g, (float)(cix + R + 1) * HCELL - pix);
        if (ciy - R > 0)        g = fminf(g, piy - (float)(ciy - R) * HCELL);
        if (ciy + R < GRID - 1) g = fminf(g, (float)(ciy + R + 1) * HCELL - piy);
        if (ciz - R > 0)        g = fminf(g, piz - (float)(ciz - R) * HCELL);
        if (ciz + R < GRID - 1) g = fminf(g, (float)(ciz + R + 1) * HCELL - piz);
        bool filled = ((unsigned)(d10key & 0xFFFFFFFFull)) != 0xFFFFFFFFu;
        float d10 = __uint_as_float((unsigned)(d10key >> 32));
        if (filled && d10 < g * g) break;
        if (R >= GRID) break;
    }

    // reduce density + covariance across the 8 lanes
#pragma unroll
    for (int o = 1; o < 8; o <<= 1) {
        cnt += __shfl_xor_sync(gmask, cnt, o);
        c00 += __shfl_xor_sync(gmask, c00, o);
        c01 += __shfl_xor_sync(gmask, c01, o);
        c02 += __shfl_xor_sync(gmask, c02, o);
        c11 += __shfl_xor_sync(gmask, c11, o);
        c12 += __shfl_xor_sync(gmask, c12, o);
        c22 += __shfl_xor_sync(gmask, c22, o);
    }

    if (l8 == 0) {
        c00 = __fdiv_rn(c00, 10.0f); c01 = __fdiv_rn(c01, 10.0f); c02 = __fdiv_rn(c02, 10.0f);
        c11 = __fdiv_rn(c11, 10.0f); c12 = __fdiv_rn(c12, 10.0f); c22 = __fdiv_rn(c22, 10.0f);
        float curv = curv_from_cov(c00, c01, c02, c11, c12, c22);

        double cm   = g_cacc[b][3];
        double cden = cm > 1.0 ? cm : 1.0;
        float cx = (float)(g_cacc[b][0] / cden);
        float cy = (float)(g_cacc[b][1] / cden);
        float cz = (float)(g_cacc[b][2] / cden);
        float rx = pix - cx, ry = piy - cy, rz = piz - cz;
        float distc = __fsqrt_rn(__fadd_rn(__fadd_rn(__fmul_rn(rx, rx), __fmul_rn(ry, ry)), __fmul_rn(rz, rz)));
        float horiz = __fsqrt_rn(__fadd_rn(__fmul_rn(rx, rx), __fmul_rn(ry, ry)));
        float rad   = atan2f(ry, rx);

        bool valid = cm > 0.0;
        g_geom[orig * 6 + 0] = valid ? distc : 0.0f;
        g_geom[orig * 6 + 1] = valid ? rz    : 0.0f;
        g_geom[orig * 6 + 2] = valid ? horiz : 0.0f;
        g_geom[orig * 6 + 3] = valid ? (float)cnt : 0.0f;
        g_geom[orig * 6 + 4] = valid ? curv  : 0.0f;
        g_geom[orig * 6 + 5] = valid ? rad   : 0.0f;
    }
}

// ================= kernel 3: fused 2-layer MLP (f32x2 FMA, 1024 threads) =================
__global__ void __launch_bounds__(NTM) k_mlp(const float* __restrict__ feat,
                                             const float* __restrict__ W1,
                                             const float* __restrict__ b1,
                                             const float* __restrict__ W2,
                                             const float* __restrict__ b2,
                                             float* __restrict__ out) {
    extern __shared__ float sm[];
    float* sW1 = sm;             // 70*128
    float* sB1 = sm + 8960;
    float* sW2 = sm + 9088;      // 128*128
    float* sB2 = sm + 25472;
    float* sX  = sm + 25600;     // 128*72
    float* sH  = sm + 34816;     // 128*132

    int tid = threadIdx.x;
    for (int i = tid; i < 8960;  i += NTM) sW1[i] = W1[i];
    for (int i = tid; i < 16384; i += NTM) sW2[i] = W2[i];
    if (tid < 128) { sB1[tid] = b1[tid]; sB2[tid] = b2[tid]; }

    int m0 = blockIdx.x * 128;
    for (int i = tid; i < 128 * 64; i += NTM) {
        int r = i >> 6, c = i & 63;
        sX[r * 72 + c] = feat[(m0 + r) * 64 + c];
    }
    if (tid < 128 * 6) {
        int r = tid / 6, c = tid % 6;
        sX[r * 72 + 64 + c] = g_geom[(m0 + r) * 6 + c];
    }
    __syncthreads();

    int cg = tid & 31;   // 32 col groups: cols cg*4 .. cg*4+3
    int rg = tid >> 5;   // 32 row groups (= warp id): rows rg*4 .. rg*4+3

    unsigned long long acc[4][2];
#pragma unroll
    for (int r = 0; r < 4; r++) { acc[r][0] = 0ull; acc[r][1] = 0ull; }

    for (int k = 0; k < 70; k++) {
        ulonglong2 w2 = *(const ulonglong2*)(sW1 + k * 128 + cg * 4);
#pragma unroll
        for (int r = 0; r < 4; r++) {
            unsigned long long xp = pack2(sX[(rg * 4 + r) * 72 + k]);   // warp-broadcast
            FMA2(acc[r][0], w2.x, xp);
            FMA2(acc[r][1], w2.y, xp);
        }
    }
    {
        float4 bv = *(const float4*)(sB1 + cg * 4);
#pragma unroll
        for (int r = 0; r < 4; r++) {
            float a0, a1, a2, a3;
            unpack2(acc[r][0], a0, a1);
            unpack2(acc[r][1], a2, a3);
            float4 h;
            h.x = fmaxf(a0 + bv.x, 0.0f);
            h.y = fmaxf(a1 + bv.y, 0.0f);
            h.z = fmaxf(a2 + bv.z, 0.0f);
            h.w = fmaxf(a3 + bv.w, 0.0f);
            *(float4*)(sH + (rg * 4 + r) * 132 + cg * 4) = h;
        }
    }
    __syncthreads();

#pragma unroll
    for (int r = 0; r < 4; r++) { acc[r][0] = 0ull; acc[r][1] = 0ull; }

    for (int k = 0; k < 128; k++) {
        ulonglong2 w2 = *(const ulonglong2*)(sW2 + k * 128 + cg * 4);
#pragma unroll
        for (int r = 0; r < 4; r++) {
            unsigned long long hp = pack2(sH[(rg * 4 + r) * 132 + k]);
            FMA2(acc[r][0], w2.x, hp);
            FMA2(acc[r][1], w2.y, hp);
        }
    }
    {
        float4 bv = *(const float4*)(sB2 + cg * 4);
#pragma unroll
        for (int r = 0; r < 4; r++) {
            float a0, a1, a2, a3;
            unpack2(acc[r][0], a0, a1);
            unpack2(acc[r][1], a2, a3);
            float4 o;
            o.x = fmaxf(a0 + bv.x, 0.0f);
            o.y = fmaxf(a1 + bv.y, 0.0f);
            o.z = fmaxf(a2 + bv.z, 0.0f);
            o.w = fmaxf(a3 + bv.w, 0.0f);
            *(float4*)(out + (size_t)(m0 + rg * 4 + r) * 128 + cg * 4) = o;
        }
    }
}

// ---------------- launch ----------------
extern "C" void kernel_launch(void* const* d_in, const int* in_sizes, int n_in,
                              void* d_out, int out_size) {
    const float* points = (const float*)d_in[0];
    const float* feat   = (const float*)d_in[1];
    const void*  mask   = d_in[2];
    const float* W1     = (const float*)d_in[3];
    const float* b1     = (const float*)d_in[4];
    const float* W2     = (const float*)d_in[5];
    const float* b2     = (const float*)d_in[6];
    float* out = (float*)d_out;

    cudaFuncSetAttribute(k_mlp, cudaFuncAttributeMaxDynamicSharedMemorySize, 212992);

    k_prep <<<NBLKP, NTHRP>>>(points, mask);
    k_geom2<<<(NPT * 8) / 256, 256>>>();
    k_mlp  <<<NPT / 128, NTM, 206848>>>(feat, W1, b1, W2, b2, out);
}

// round 13
// speedup vs baseline: 2.2657x; 1.0795x over previous
#include <cuda_runtime.h>
#include <math.h>

#define BB 2
#define NN 8192
#define NPT (BB*NN)
#define KNN 10
#define GRID 16
#define GC (GRID*GRID*GRID)
#define HCELL 0.0625f
#define NBLKP 128
#define NTHRP 256
#define PEPS 1e-6f

// ---------------- device scratch ----------------
__device__ float4 g_sp4[NPT];
__device__ int    g_sidx[NPT];
__device__ int    g_cnt[BB*GC];      // INVARIANT: zero at kernel entry
__device__ int2   g_range[BB*GC];
__device__ int    g_cur[BB*GC];
__device__ double g_cacc[BB][4];
__device__ float  g_geom[NPT * 6];
__device__ int    g_mtype;
__device__ float  g_T;
__device__ unsigned g_barcnt = 0;
__device__ unsigned g_sense  = 0;

// ---------------- grid barrier ----------------
__device__ __forceinline__ void gridbar() {
    __syncthreads();
    if (threadIdx.x == 0) {
        __threadfence();
        unsigned gen = atomicAdd(&g_sense, 0u);
        if (atomicAdd(&g_barcnt, 1u) == NBLKP - 1) {
            g_barcnt = 0;
            __threadfence();
            atomicAdd(&g_sense, 1u);
        } else {
            while (atomicAdd(&g_sense, 0u) == gen) {}
        }
        __threadfence();
    }
    __syncthreads();
}

__device__ __forceinline__ int cell_of(float x, float y, float z) {
    int cx = min(GRID - 1, max(0, (int)(x * (float)GRID)));
    int cy = min(GRID - 1, max(0, (int)(y * (float)GRID)));
    int cz = min(GRID - 1, max(0, (int)(z * (float)GRID)));
    return (cz * GRID + cy) * GRID + cx;
}

__device__ __forceinline__ bool read_mask(const void* mp, int i, int mt) {
    if (mt & 1) return ((const unsigned char*)mp)[i] != 0;
    if (mt & 2) return ((const float*)mp)[i] != 0.0f;
    return ((const int*)mp)[i] != 0;
}

// ================= kernel 1: prep (identical to R11) =================
__global__ void __launch_bounds__(NTHRP)
k_prep(const float* __restrict__ pts, const void* __restrict__ mask) {
    const int tid = threadIdx.x;
    const int bid = blockIdx.x;
    const int gid = bid * NTHRP + tid;

    {
        bool act = gid < NPT;
        unsigned char mb = 0;
        if (act) {
            float x = pts[gid * 3 + 0], y = pts[gid * 3 + 1], z = pts[gid * 3 + 2];
            mb = ((const unsigned char*)mask)[gid];
            atomicAdd(&g_cnt[(gid >> 13) * GC + cell_of(x, y, z)], 1);
        }
        int r = gid & 3;
        unsigned m1 = __ballot_sync(0xFFFFFFFFu, act && (r == 1) && mb);
        unsigned m2 = __ballot_sync(0xFFFFFFFFu, act && (r >= 2) && mb);
        if ((tid & 31) == 0 && (m1 | m2))
            atomicOr(&g_mtype, (m1 ? 1 : 0) | (m2 ? 2 : 0));
    }
    gridbar();

    if (bid < BB) {
        __shared__ int part[NTHRP];
        int base = bid * GC + tid * 16;
        int loc[16]; int s = 0;
#pragma unroll
        for (int k = 0; k < 16; k++) { loc[k] = s; s += g_cnt[base + k]; }
        part[tid] = s;
        __syncthreads();
        for (int d = 1; d < NTHRP; d <<= 1) {
            int v = (tid >= d) ? part[tid - d] : 0;
            __syncthreads();
            part[tid] += v;
            __syncthreads();
        }
        int off = part[tid] - s;
#pragma unroll
        for (int k = 0; k < 16; k++) {
            int st = off + loc[k];
            int ln = g_cnt[base + k];
            g_range[base + k] = make_int2(st, st + ln);
            g_cur[base + k]   = st;
            g_cnt[base + k]   = 0;
        }
        if (gid == 0) {
            for (int b = 0; b < BB; b++)
                for (int c = 0; c < 4; c++) g_cacc[b][c] = 0.0;
            const float R = 0.02f;
            float t = __fmul_rn(R, R);
            while (__fsqrt_rn(t) >= R) t = __uint_as_float(__float_as_uint(t) - 1u);
            for (;;) {
                float nt = __uint_as_float(__float_as_uint(t) + 1u);
                if (__fsqrt_rn(nt) < R) t = nt; else break;
            }
            g_T = t;
        }
    }
    gridbar();

    if (gid < NPT) {
        int mt = g_mtype;
        float x = pts[gid * 3 + 0], y = pts[gid * 3 + 1], z = pts[gid * 3 + 2];
        float sq = __fadd_rn(__fadd_rn(__fmul_rn(x, x), __fmul_rn(y, y)), __fmul_rn(z, z));
        int b = gid >> 13;
        int cell = b * GC + cell_of(x, y, z);
        bool mk = read_mask(mask, gid, mt);
        float wv = mk ? __uint_as_float(__float_as_uint(sq) | 0x80000000u) : sq;
        int pos = atomicAdd(&g_cur[cell], 1);
        int dst = b * NN + pos;
        g_sp4[dst]  = make_float4(x, y, z, wv);
        g_sidx[dst] = gid;
        double vx = mk ? (double)x : 0.0, vy = mk ? (double)y : 0.0;
        double vz = mk ? (double)z : 0.0, vc = mk ? 1.0 : 0.0;
#pragma unroll
        for (int o = 16; o > 0; o >>= 1) {
            vx += __shfl_down_sync(0xFFFFFFFFu, vx, o);
            vy += __shfl_down_sync(0xFFFFFFFFu, vy, o);
            vz += __shfl_down_sync(0xFFFFFFFFu, vz, o);
            vc += __shfl_down_sync(0xFFFFFFFFu, vc, o);
        }
        if ((tid & 31) == 0) {
            atomicAdd(&g_cacc[b][0], vx);
            atomicAdd(&g_cacc[b][1], vy);
            atomicAdd(&g_cacc[b][2], vz);
            atomicAdd(&g_cacc[b][3], vc);
        }
    }
}

// ---------------- analytic eigenvalues of symmetric 3x3 (fp64) ----------------
__device__ __forceinline__ float curv_from_cov(float c00, float c01, float c02,
                                               float c11, float c12, float c22) {
    double a00 = c00, a01 = c01, a02 = c02, a11 = c11, a12 = c12, a22 = c22;
    double p1 = a01 * a01 + a02 * a02 + a12 * a12;
    double q  = (a00 + a11 + a22) / 3.0;
    double d0 = a00 - q, d1 = a11 - q, d2v = a22 - q;
    double p2 = d0 * d0 + d1 * d1 + d2v * d2v + 2.0 * p1;
    double emin, emax;
    if (!(p2 > 0.0)) { emin = q; emax = q; }
    else {
        double p = sqrt(p2 / 6.0);
        double ip = 1.0 / p;
        double b00 = d0 * ip, b11 = d1 * ip, b22 = d2v * ip;
        double b01 = a01 * ip, b02 = a02 * ip, b12 = a12 * ip;
        double detB = b00 * (b11 * b22 - b12 * b12)
                    - b01 * (b01 * b22 - b12 * b02)
                    + b02 * (b01 * b12 - b11 * b02);
        double r = 0.5 * detB;
        r = fmin(1.0, fmax(-1.0, r));
        double phi = acos(r) / 3.0;
        emax = q + 2.0 * p * cos(phi);
        emin = q + 2.0 * p * cos(phi + 2.0943951023931953);
    }
    float e0 = (float)emin, e2 = (float)emax;
    return e0 / (e2 + 1e-8f);
}

// ================= kernel 2: geom (identical to R11) =================
__global__ void __launch_bounds__(256) k_geom2() {
    const int gt = blockIdx.x * 256 + threadIdx.x;
    const int p  = gt >> 3;
    const int l8 = gt & 7;
    const int b  = p >> 13;
    const int s  = p & (NN - 1);
    const int boff  = b * NN;
    const int cbase = b * GC;
    const unsigned gmask = 0xFFu << ((threadIdx.x & 31) & ~7);

    float4 pi = __ldg(&g_sp4[boff + s]);
    const float pix = pi.x, piy = pi.y, piz = pi.z, piw = fabsf(pi.w);
    const int orig  = g_sidx[boff + s];
    const float Tloc = g_T;

    const int cix = min(GRID - 1, max(0, (int)(pix * (float)GRID)));
    const int ciy = min(GRID - 1, max(0, (int)(piy * (float)GRID)));
    const int ciz = min(GRID - 1, max(0, (int)(piz * (float)GRID)));

    float r_est = 0.075f;
#pragma unroll
    for (int it = 0; it < 2; it++) {
        float fx = (fminf(pix + r_est, 1.0f) - fmaxf(pix - r_est, 0.0f)) / (2.0f * r_est);
        float fy = (fminf(piy + r_est, 1.0f) - fmaxf(piy - r_est, 0.0f)) / (2.0f * r_est);
        float fz = (fminf(piz + r_est, 1.0f) - fmaxf(piz - r_est, 0.0f)) / (2.0f * r_est);
        r_est = cbrtf(6.4e-4f / fmaxf(fx * fy * fz, 0.125f));
    }
    const float t_est = r_est * r_est;
    const unsigned long long GATE_EST =
        ((unsigned long long)__float_as_uint(t_est) << 32) | 0xFFFFFFFFull;
    const unsigned long long GATE_INF = 0xFFFFFFFFFFFFFFFFull;

    unsigned long long best[KNN];
    int cnt;
    float c00, c01, c02, c11, c12, c22;
    unsigned long long d10key;

    for (int R = 2;; R++) {
        bool scanned = false;

        if (R == 2) {
#pragma unroll
            for (int k = 0; k < KNN; k++) best[k] = GATE_EST;
            cnt = 0;
            int passes = 0;

            const int x0 = max(cix - 2, 0), x1 = min(cix + 2, GRID - 1);
            int rjst[4], rjen[4];
#pragma unroll
            for (int i = 0; i < 4; i++) {
                rjst[i] = 0; rjen[i] = 0;
                int q = l8 + 8 * i;
                if (q < 25) {
                    int zz = ciz + q / 5 - 2, yy = ciy + q % 5 - 2;
                    if ((unsigned)zz < GRID && (unsigned)yy < GRID) {
                        float zlo = (float)zz * HCELL, zhi = zlo + HCELL;
                        float ylo = (float)yy * HCELL, yhi = ylo + HCELL;
                        float dzl = fmaxf(0.0f, fmaxf(zlo - piz, piz - zhi));
                        float dyl = fmaxf(0.0f, fmaxf(ylo - piy, piy - yhi));
                        float rb2 = dzl * dzl + dyl * dyl;
                        if (rb2 <= t_est + PEPS) {
                            float xr = sqrtf(t_est + PEPS - rb2);
                            int xlo = (int)((pix - xr) * (float)GRID);
                            int xhi = (int)((pix + xr) * (float)GRID);
                            int xa = max(x0, xlo), xb = min(x1, xhi);
                            int crow = cbase + (zz * GRID + yy) * GRID;
                            rjst[i] = __ldg(&g_range[crow + xa].x);
                            rjen[i] = __ldg(&g_range[crow + xb].y);
                        }
                    }
                }
            }
#pragma unroll
            for (int i = 0; i < 4; i++) {
#pragma unroll 2
                for (int j = rjst[i]; j < rjen[i]; ++j) {
                    float4 pj = __ldg(&g_sp4[boff + j]);
                    float sqj = fabsf(pj.w);
                    float Tv  = (__float_as_uint(pj.w) & 0x80000000u)
                                ? Tloc : __int_as_float(0xff800000);
                    float dot = fmaf(pix, pj.x, fmaf(piy, pj.y, piz * pj.z));
                    float d2  = fmaf(-2.0f, dot, piw + sqj);
                    if (d2 <= Tv) cnt++;
                    float d2c = fmaxf(d2, 0.0f);
                    if (d2c < t_est) passes++;
                    unsigned long long key =
                        ((unsigned long long)__float_as_uint(d2c) << 32) | (unsigned)j;
                    if (key < best[KNN - 1]) {
#pragma unroll
                        for (int k = 0; k < KNN; k++) {
                            if (key < best[k]) {
                                unsigned long long tmp = best[k]; best[k] = key; key = tmp;
                            }
                        }
                    }
                }
            }

            int pall = passes;
            pall += __shfl_xor_sync(gmask, pall, 1);
            pall += __shfl_xor_sync(gmask, pall, 2);
            pall += __shfl_xor_sync(gmask, pall, 4);
            if (pall >= KNN) scanned = true;
        }

        if (!scanned) {
#pragma unroll
            for (int k = 0; k < KNN; k++) best[k] = GATE_INF;
            cnt = 0;

            const int W = 2 * R + 1;
            const int nr = W * W;
            const int x0 = max(cix - R, 0), x1 = min(cix + R, GRID - 1);
            int qy = l8, qz = 0;
            while (qy >= W) { qy -= W; qz++; }

            for (int q = l8; q < nr; q += 8) {
                int zz = ciz + qz - R, yy = ciy + qy - R;
                if ((unsigned)zz < GRID && (unsigned)yy < GRID) {
                    int crow = cbase + (zz * GRID + yy) * GRID;
                    int jst = __ldg(&g_range[crow + x0].x);
                    int jen = __ldg(&g_range[crow + x1].y);
                    for (int j = jst; j < jen; ++j) {
                        float4 pj = __ldg(&g_sp4[boff + j]);
                        float sqj = fabsf(pj.w);
                        float Tv  = (__float_as_uint(pj.w) & 0x80000000u)
                                    ? Tloc : __int_as_float(0xff800000);
                        float dot = fmaf(pix, pj.x, fmaf(piy, pj.y, piz * pj.z));
                        float d2  = fmaf(-2.0f, dot, piw + sqj);
                        if (d2 <= Tv) cnt++;
                        float d2c = fmaxf(d2, 0.0f);
                        unsigned long long key =
                            ((unsigned long long)__float_as_uint(d2c) << 32) | (unsigned)j;
                        if (key < best[KNN - 1]) {
#pragma unroll
                            for (int k = 0; k < KNN; k++) {
                                if (key < best[k]) {
                                    unsigned long long tmp = best[k]; best[k] = key; key = tmp;
                                }
                            }
                        }
                    }
                }
                qy += 8;
                while (qy >= W) { qy -= W; qz++; }
            }
        }

        c00 = c01 = c02 = c11 = c12 = c22 = 0.0f;
        d10key = GATE_INF;
#pragma unroll
        for (int round = 0; round < KNN; round++) {
            unsigned long long m = best[0];
            m = min(m, __shfl_xor_sync(gmask, m, 1));
            m = min(m, __shfl_xor_sync(gmask, m, 2));
            m = min(m, __shfl_xor_sync(gmask, m, 4));
            bool real = ((unsigned)(m & 0xFFFFFFFFull)) != 0xFFFFFFFFu;
            if (m == best[0] && real) {
                int j = (int)(unsigned)(m & 0xFFFFFFFFull);
                float4 q = __ldg(&g_sp4[boff + j]);
                float dx = q.x - pix, dy = q.y - piy, dz = q.z - piz;
                c00 = fmaf(dx, dx, c00); c01 = fmaf(dx, dy, c01); c02 = fmaf(dx, dz, c02);
                c11 = fmaf(dy, dy, c11); c12 = fmaf(dy, dz, c12); c22 = fmaf(dz, dz, c22);
#pragma unroll
                for (int k = 0; k < KNN - 1; k++) best[k] = best[k + 1];
                best[KNN - 1] = GATE_INF;
            }
            d10key = m;
        }

        float g = __int_as_float(0x7f800000);
        if (cix - R > 0)        g = fminf(g, pix - (float)(cix - R) * HCELL);
        if (cix + R < GRID - 1) g = fminf(g, (float)(cix + R + 1) * HCELL - pix);
        if (ciy - R > 0)        g = fminf(g, piy - (float)(ciy - R) * HCELL);
        if (ciy + R < GRID - 1) g = fminf(g, (float)(ciy + R + 1) * HCELL - piy);
        if (ciz - R > 0)        g = fminf(g, piz - (float)(ciz - R) * HCELL);
        if (ciz + R < GRID - 1) g = fminf(g, (float)(ciz + R + 1) * HCELL - piz);
        bool filled = ((unsigned)(d10key & 0xFFFFFFFFull)) != 0xFFFFFFFFu;
        float d10 = __uint_as_float((unsigned)(d10key >> 32));
        if (filled && d10 < g * g) break;
        if (R >= GRID) break;
    }

#pragma unroll
    for (int o = 1; o < 8; o <<= 1) {
        cnt += __shfl_xor_sync(gmask, cnt, o);
        c00 += __shfl_xor_sync(gmask, c00, o);
        c01 += __shfl_xor_sync(gmask, c01, o);
        c02 += __shfl_xor_sync(gmask, c02, o);
        c11 += __shfl_xor_sync(gmask, c11, o);
        c12 += __shfl_xor_sync(gmask, c12, o);
        c22 += __shfl_xor_sync(gmask, c22, o);
    }

    if (l8 == 0) {
        c00 = __fdiv_rn(c00, 10.0f); c01 = __fdiv_rn(c01, 10.0f); c02 = __fdiv_rn(c02, 10.0f);
        c11 = __fdiv_rn(c11, 10.0f); c12 = __fdiv_rn(c12, 10.0f); c22 = __fdiv_rn(c22, 10.0f);
        float curv = curv_from_cov(c00, c01, c02, c11, c12, c22);

        double cm   = g_cacc[b][3];
        double cden = cm > 1.0 ? cm : 1.0;
        float cx = (float)(g_cacc[b][0] / cden);
        float cy = (float)(g_cacc[b][1] / cden);
        float cz = (float)(g_cacc[b][2] / cden);
        float rx = pix - cx, ry = piy - cy, rz = piz - cz;
        float distc = __fsqrt_rn(__fadd_rn(__fadd_rn(__fmul_rn(rx, rx), __fmul_rn(ry, ry)), __fmul_rn(rz, rz)));
        float horiz = __fsqrt_rn(__fadd_rn(__fmul_rn(rx, rx), __fmul_rn(ry, ry)));
        float rad   = atan2f(ry, rx);

        bool valid = cm > 0.0;
        g_geom[orig * 6 + 0] = valid ? distc : 0.0f;
        g_geom[orig * 6 + 1] = valid ? rz    : 0.0f;
        g_geom[orig * 6 + 2] = valid ? horiz : 0.0f;
        g_geom[orig * 6 + 3] = valid ? (float)cnt : 0.0f;
        g_geom[orig * 6 + 4] = valid ? curv  : 0.0f;
        g_geom[orig * 6 + 5] = valid ? rad   : 0.0f;
    }
}

// ================= kernel 3: MLP via warp-level mma.sync (tf32) =================
// smem layout (floats): sX[128][76] @0 | sW1[72][136] @9728 | sW2[128][136] @19520
//                       sH[128][132] @36928 | sB1 @53824 | sB2 @53952   (216,320 B)
#define XS   76
#define WS   136
#define HS   132
#define OX   0
#define OW1  9728
#define OW2  19520
#define OH   36928
#define OB1  53824
#define OB2  53952
#define SMEM_MMA 216320

__device__ __forceinline__ unsigned to_tf32u(float v) {
    unsigned r; asm("cvt.rna.tf32.f32 %0, %1;" : "=r"(r) : "f"(v)); return r;
}
__device__ __forceinline__ void mma8(float* c, unsigned a0, unsigned a1, unsigned a2,
                                     unsigned a3, unsigned b0, unsigned b1) {
    asm volatile(
        "mma.sync.aligned.m16n8k8.row.col.f32.tf32.tf32.f32 "
        "{%0,%1,%2,%3}, {%4,%5,%6,%7}, {%8,%9}, {%0,%1,%2,%3};"
        : "+f"(c[0]), "+f"(c[1]), "+f"(c[2]), "+f"(c[3])
        : "r"(a0), "r"(a1), "r"(a2), "r"(a3), "r"(b0), "r"(b1));
}

__global__ void __launch_bounds__(256)
k_mlp_mma(const float* __restrict__ feat,
          const float* __restrict__ W1, const float* __restrict__ b1,
          const float* __restrict__ W2, const float* __restrict__ b2,
          float* __restrict__ out) {
    extern __shared__ float sm[];
    const int tid = threadIdx.x;
    const int wid = tid >> 5;
    const int lane = tid & 31;
    const int lr = lane >> 2;      // 0..7
    const int lc = lane & 3;       // 0..3
    const int wrow = wid * 16;     // warp's 16-row stripe
    const int m0 = blockIdx.x * 128;

    // ---- stage inputs (tf32-rounded) ----
    for (int i = tid; i < 128 * 64; i += 256) {
        int r = i >> 6, c = i & 63;
        sm[OX + r * XS + c] = __uint_as_float(to_tf32u(feat[(size_t)(m0 + r) * 64 + c]));
    }
    for (int i = tid; i < 128 * 6; i += 256) {
        int r = i / 6, c = i % 6;
        sm[OX + r * XS + 64 + c] = __uint_as_float(to_tf32u(g_geom[(size_t)(m0 + r) * 6 + c]));
    }
    if (tid < 256) {               // X pad cols 70,71 = 0
        int r = tid >> 1, c = 70 + (tid & 1);
        sm[OX + r * XS + c] = 0.0f;
    }
    for (int i = tid; i < 70 * 128; i += 256) {
        int k = i >> 7, n = i & 127;
        sm[OW1 + k * WS + n] = __uint_as_float(to_tf32u(W1[i]));
    }
    if (tid < 256) {               // W1 pad rows 70,71 = 0
        int k = 70 + (tid >> 7), n = tid & 127;
        sm[OW1 + k * WS + n] = 0.0f;
    }
    for (int i = tid; i < 128 * 128; i += 256) {
        int k = i >> 7, n = i & 127;
        sm[OW2 + k * WS + n] = __uint_as_float(to_tf32u(W2[i]));
    }
    if (tid < 128) { sm[OB1 + tid] = b1[tid]; sm[OB2 + tid] = b2[tid]; }
    __syncthreads();

    float acc[16][4];
#pragma unroll
    for (int t = 0; t < 16; t++)
#pragma unroll
        for (int c = 0; c < 4; c++) acc[t][c] = 0.0f;

    // ---- layer 1: X[128x72] @ W1t -> acc (9 k-steps) ----
    const float* xa = sm + OX + (wrow + lr) * XS;
    for (int ks = 0; ks < 9; ks++) {
        int k0 = ks * 8;
        unsigned a0 = __float_as_uint(xa[k0 + lc]);
        unsigned a1 = __float_as_uint(xa[8 * XS + k0 + lc]);
        unsigned a2 = __float_as_uint(xa[k0 + lc + 4]);
        unsigned a3 = __float_as_uint(xa[8 * XS + k0 + lc + 4]);
        const float* wb = sm + OW1 + (k0 + lc) * WS + lr;
#pragma unroll
        for (int t = 0; t < 16; t++) {
            unsigned b0 = __float_as_uint(wb[t * 8]);
            unsigned b1r = __float_as_uint(wb[4 * WS + t * 8]);
            mma8(acc[t], a0, a1, a2, a3, b0, b1r);
        }
    }

    // ---- epilogue 1: bias + relu -> H (tf32, warp-local rows) ----
#pragma unroll
    for (int t = 0; t < 16; t++) {
        int n0 = t * 8 + 2 * lc;
        float bv0 = sm[OB1 + n0], bv1 = sm[OB1 + n0 + 1];
        float2 h0, h1;
        h0.x = __uint_as_float(to_tf32u(fmaxf(acc[t][0] + bv0, 0.0f)));
        h0.y = __uint_as_float(to_tf32u(fmaxf(acc[t][1] + bv1, 0.0f)));
        h1.x = __uint_as_float(to_tf32u(fmaxf(acc[t][2] + bv0, 0.0f)));
        h1.y = __uint_as_float(to_tf32u(fmaxf(acc[t][3] + bv1, 0.0f)));
        *(float2*)&sm[OH + (wrow + lr) * HS + n0]     = h0;
        *(float2*)&sm[OH + (wrow + lr + 8) * HS + n0] = h1;
    }
    __syncwarp();   // H rows are warp-local: no block sync needed

#pragma unroll
    for (int t = 0; t < 16; t++)
#pragma unroll
        for (int c = 0; c < 4; c++) acc[t][c] = 0.0f;

    // ---- layer 2: H[128x128] @ W2t -> acc (16 k-steps) ----
    const float* ha = sm + OH + (wrow + lr) * HS;
    for (int ks = 0; ks < 16; ks++) {
        int k0 = ks * 8;
        unsigned a0 = __float_as_uint(ha[k0 + lc]);
        unsigned a1 = __float_as_uint(ha[8 * HS + k0 + lc]);
        unsigned a2 = __float_as_uint(ha[k0 + lc + 4]);
        unsigned a3 = __float_as_uint(ha[8 * HS + k0 + lc + 4]);
        const float* wb = sm + OW2 + (k0 + lc) * WS + lr;
#pragma unroll
        for (int t = 0; t < 16; t++) {
            unsigned b0 = __float_as_uint(wb[t * 8]);
            unsigned b1r = __float_as_uint(wb[4 * WS + t * 8]);
            mma8(acc[t], a0, a1, a2, a3, b0, b1r);
        }
    }

    // ---- epilogue 2: bias + relu -> global (float2 stores) ----
#pragma unroll
    for (int t = 0; t < 16; t++) {
        int n0 = t * 8 + 2 * lc;
        float bv0 = sm[OB2 + n0], bv1 = sm[OB2 + n0 + 1];
        float2 o0, o1;
        o0.x = fmaxf(acc[t][0] + bv0, 0.0f);
        o0.y = fmaxf(acc[t][1] + bv1, 0.0f);
        o1.x = fmaxf(acc[t][2] + bv0, 0.0f);
        o1.y = fmaxf(acc[t][3] + bv1, 0.0f);
        *(float2*)&out[(size_t)(m0 + wrow + lr) * 128 + n0]     = o0;
        *(float2*)&out[(size_t)(m0 + wrow + lr + 8) * 128 + n0] = o1;
    }
}

// ---------------- launch ----------------
extern "C" void kernel_launch(void* const* d_in, const int* in_sizes, int n_in,
                              void* d_out, int out_size) {
    const float* points = (const float*)d_in[0];
    const float* feat   = (const float*)d_in[1];
    const void*  mask   = d_in[2];
    const float* W1     = (const float*)d_in[3];
    const float* b1     = (const float*)d_in[4];
    const float* W2     = (const float*)d_in[5];
    const float* b2     = (const float*)d_in[6];
    float* out = (float*)d_out;

    cudaFuncSetAttribute(k_mlp_mma, cudaFuncAttributeMaxDynamicSharedMemorySize, SMEM_MMA);

    k_prep   <<<NBLKP, NTHRP>>>(points, mask);
    k_geom2  <<<(NPT * 8) / 256, 256>>>();
    k_mlp_mma<<<NPT / 128, 256, SMEM_MMA>>>(feat, W1, b1, W2, b2, out);
}